// round 13
// baseline (speedup 1.0000x reference)
#include <cuda_runtime.h>
#include <cuda_fp16.h>
#include <cstdint>

#define NB 32
#define CH 128
#define PP 4096        // H*W
#define K3 384         // 3*C  (k' = m*128 + cp m-major order everywhere)
#define SPLITS 4       // split-K for t9 (over p)
#define NSTG 4         // cp.async pipeline depth

// swizzled smem tile sizes (bytes)
#define A_BYTES 8192   // 128 rows x 64B, XOR-swizzled
#define B_BYTES 8192   // 32 rows x 256B ([k][n]) or 128x64B ([n][k]), swizzled
#define STG_BYTES (A_BYTES + B_BYTES)   // 16384

// fp32 scratch (split-K partials only)
__device__ float g_t9p[SPLITS * NB * CH * K3];
// fp16 single operands everywhere
__device__ __half g_w3r[CH * K3];
__device__ __half g_w6r[CH * K3];
__device__ __half g_t1s[NB * K3 * PP];   // t1m [nb][k'][p]
__device__ __half g_t5s[NB * CH * PP];
__device__ __half g_t3s[NB * CH * PP];
__device__ __half g_t6s[NB * CH * PP];
__device__ __half g_t7s[NB * CH * PP];
__device__ __half g_t12s[NB * K3 * PP];  // rows k'
__device__ __half g_t9s [NB * CH * K3]; // cols k'

// ---------------------------------------------------------------------------
__device__ __forceinline__ unsigned pack2h(float v0, float v1)
{
    __half2 hh = __halves2half2(__float2half(v0), __float2half(v1));
    return *reinterpret_cast<unsigned*>(&hh);
}

__device__ __forceinline__ void mma_f16(float& d0, float& d1, float& d2, float& d3,
                                        unsigned a0, unsigned a1, unsigned a2, unsigned a3,
                                        unsigned b0, unsigned b1)
{
    asm volatile(
        "mma.sync.aligned.m16n8k16.row.col.f32.f16.f16.f32 "
        "{%0,%1,%2,%3},{%4,%5,%6,%7},{%8,%9},{%0,%1,%2,%3};\n"
        : "+f"(d0), "+f"(d1), "+f"(d2), "+f"(d3)
        : "r"(a0), "r"(a1), "r"(a2), "r"(a3), "r"(b0), "r"(b1));
}

__device__ __forceinline__ void ldsm4(unsigned& r0, unsigned& r1, unsigned& r2, unsigned& r3, unsigned a)
{
    asm volatile("ldmatrix.sync.aligned.m8n8.x4.shared.b16 {%0,%1,%2,%3},[%4];"
                 : "=r"(r0), "=r"(r1), "=r"(r2), "=r"(r3) : "r"(a));
}
__device__ __forceinline__ void ldsm4t(unsigned& r0, unsigned& r1, unsigned& r2, unsigned& r3, unsigned a)
{
    asm volatile("ldmatrix.sync.aligned.m8n8.x4.trans.shared.b16 {%0,%1,%2,%3},[%4];"
                 : "=r"(r0), "=r"(r1), "=r"(r2), "=r"(r3) : "r"(a));
}
__device__ __forceinline__ void cp16(unsigned d, const void* s)
{
    asm volatile("cp.async.ca.shared.global [%0], [%1], 16;" :: "r"(d), "l"(s));
}
__device__ __forceinline__ void cp16z(unsigned d, const void* s, int sz)
{
    asm volatile("cp.async.ca.shared.global [%0], [%1], 16, %2;" :: "r"(d), "l"(s), "r"(sz));
}

// A-style tile: 128 rows x 32 halfs (64B). Two rows share a 128B line;
// chunk slot = ((r&1)*4 + c) ^ ((r>>1)&7)  -> conflict-free ldsm + stores.
__device__ __forceinline__ int aswz(int row, int c0)
{
    return (row >> 1) * 128 + (((((row & 1) << 2) | c0) ^ ((row >> 1) & 7)) << 4);
}
// B [k][n] tile: 32 rows x 128 halfs (256B rows, 16 chunks); slot = c ^ (k&7).
__device__ __forceinline__ int bswz(int row, int cb)
{
    return row * 256 + ((cb ^ (row & 7)) << 4);
}

// ---------------------------------------------------------------------------
// Prep kernels (unchanged numerics)
// ---------------------------------------------------------------------------
__global__ void prep_w_kernel(const float* __restrict__ w3, const float* __restrict__ w6)
{
    int idx = blockIdx.x * 256 + threadIdx.x;
    int half_n = CH * K3 / 2;
    const float* src = (idx < half_n) ? w3 : w6;
    __half* dh = (idx < half_n) ? g_w3r : g_w6r;
    int i2 = (idx % half_n) * 2;
    int o = i2 / K3;
    int kp = i2 - o * K3;
    int m = kp >> 7;
    int cp = kp & 127;
    *reinterpret_cast<unsigned*>(&dh[i2]) =
        pack2h(src[o * K3 + 3 * cp + m], src[o * K3 + 3 * (cp + 1) + m]);
}

__global__ void prep_t1m_kernel(const float* __restrict__ x)
{
    int i2 = (blockIdx.x * 256 + threadIdx.x) * 2;
    int p = i2 & (PP - 1);
    int r = i2 >> 12;
    int kp = r % K3;
    int nb = r / K3;
    int m = kp >> 7, cp = kp & 127;
    int w = p & 63;
    const float* xr = x + (size_t)(nb * CH + cp) * PP + (p - w);
    int sh = 2 * m - 2;
    float v0 = ((unsigned)(w + sh)     < 64u) ? xr[w + sh]     : 0.f;
    float v1 = ((unsigned)(w + 1 + sh) < 64u) ? xr[w + 1 + sh] : 0.f;
    *reinterpret_cast<unsigned*>(&g_t1s[i2]) = pack2h(v0, v1);
}

__global__ void prep_t5_kernel(const float* __restrict__ x, const float* __restrict__ p5)
{
    int i2 = (blockIdx.x * 256 + threadIdx.x) * 2;
    if (i2 >= NB * CH * PP) return;
    int p = i2 & (PP - 1);
    int w = p & 63;
    const float* xr = x + (i2 - w);
    float v[2];
#pragma unroll
    for (int e = 0; e < 2; e++) {
        int we = w + e;
        float mx = xr[we];
        if (we >= 2) mx = fmaxf(mx, xr[we - 2]);
        if (we < 62) mx = fmaxf(mx, xr[we + 2]);
        v[e] = p5[p - w + we] * mx;
    }
    *reinterpret_cast<unsigned*>(&g_t5s[i2]) = pack2h(v[0], v[1]);
}

__global__ void prep_t12_kernel(const float* __restrict__ x, const float* __restrict__ p12)
{
    int i2 = (blockIdx.x * 256 + threadIdx.x) * 2;
    int p = i2 & (PP - 1);
    int r = i2 >> 12;
    int kp = r % K3;
    int nb = r / K3;
    int j  = kp >> 7;
    int cp = kp & 127;
    int h = p >> 6;
    int w = p & 63;
    size_t base = ((size_t)nb * CH + cp) * PP + p;
    float sc = p12[j * 64 + h];
    __half2 h6 = *reinterpret_cast<const __half2*>(&g_t6s[base]);
    __half2 h3 = *reinterpret_cast<const __half2*>(&g_t3s[base]);
    float2 f6 = __half22float2(h6);
    float2 f3 = __half22float2(h3);
    float v[2];
#pragma unroll
    for (int e = 0; e < 2; e++) {
        float xv  = x[base + e];
        float t6v = (e == 0) ? f6.x : f6.y;
        float t3v = (e == 0) ? f3.x : f3.y;
        int wq = w + e + 2 * j - 2;
        float x1 = ((unsigned)wq < 64u) ? x[base + e - (w + e) + wq] : 0.f;
        v[e] = sc * fmaxf(t6v, fmaxf(xv, t6v) + fmaxf(t3v, x1));
    }
    *reinterpret_cast<unsigned*>(&g_t12s[i2]) = pack2h(v[0], v[1]);
}

__global__ void reduce_t9s_kernel()
{
    int i2 = (blockIdx.x * 256 + threadIdx.x) * 2;
    float s0 = 0.f, s1 = 0.f;
#pragma unroll
    for (int u = 0; u < SPLITS; u++) {
        s0 += g_t9p[(size_t)u * NB * CH * K3 + i2];
        s1 += g_t9p[(size_t)u * NB * CH * K3 + i2 + 1];
    }
    *reinterpret_cast<unsigned*>(&g_t9s[i2]) =
        pack2h(s0 * (1.0f / 64.0f), s1 * (1.0f / 64.0f));
}

// ---------------------------------------------------------------------------
// mma.sync GEMM — 256 threads (8 warps 2m x 4n, warp tile 64x32), 1 MMA,
// 4-stage cp.async pipeline, XOR-swizzled smem (conflict-free ldmatrix).
//   MODE 0: t3  = w3r @ t1s        K=384   -> g_t3s (fp16)
//   MODE 1: t6  = w6r @ t5s(hsh)   K=384   -> g_t6s + fused t7 epilogue
//   MODE 2: t9p = t7s @ t1s^T      K=1024 slab -> g_t9p (fp32)
//   MODE 3: out = t9s @ t12s       K=384   -> out (fp32, scaled)
// ---------------------------------------------------------------------------
template <int MODE>
__global__ void __launch_bounds__(256, 2)
mma_gemm_kernel(const float* __restrict__ x, const float* __restrict__ p8,
                float* __restrict__ Cdst)
{
    extern __shared__ __half smbuf[];
    const int KTOT    = (MODE == 2) ? (PP / SPLITS) : K3;
    const int nb      = blockIdx.y;
    const int nt0     = blockIdx.x * 128;
    const int kbase   = (MODE == 2) ? blockIdx.z * (PP / SPLITS) : 0;

    const int tid = threadIdx.x;
    const int wid = tid >> 5, lane = tid & 31;
    const int gq = lane >> 2, cq = lane & 3;
    const int lr = lane & 15;
    const int wm = (wid >> 2) * 64, wn = (wid & 3) * 32;
    const int h0 = nt0 >> 6;

    const unsigned sm0 = (unsigned)__cvta_generic_to_shared(smbuf);

    const __half *srcA;
    int strideA;
    if (MODE == 0)      { srcA = g_w3r; strideA = K3; }
    else if (MODE == 1) { srcA = g_w6r; strideA = K3; }
    else if (MODE == 2) { srcA = g_t7s + (size_t)nb * CH * PP + kbase; strideA = PP; }
    else                { srcA = g_t9s + (size_t)nb * CH * K3; strideA = K3; }

    const __half* srcB2 = g_t1s + ((size_t)nb * K3 + nt0) * PP + kbase;

    float acc[4][4][4];
#pragma unroll
    for (int i = 0; i < 4; i++)
#pragma unroll
        for (int j = 0; j < 4; j++)
#pragma unroll
            for (int q = 0; q < 4; q++) acc[i][j][q] = 0.f;

    auto issue_stage = [&](int kt, int buf) {
        const unsigned sb = sm0 + buf * STG_BYTES;
        // A: 128 rows x 32 halfs, 512 16B-chunks over 256 threads, swizzled
#pragma unroll
        for (int q = 0; q < 2; q++) {
            int c = tid + q * 256;
            int row = c >> 2, c0 = c & 3;
            cp16(sb + aswz(row, c0), srcA + (size_t)row * strideA + kt + c0 * 8);
        }
        // B
        if (MODE == 2) {
#pragma unroll
            for (int q = 0; q < 2; q++) {
                int c = tid + q * 256;
                int row = c >> 2, c0 = c & 3;
                cp16(sb + A_BYTES + aswz(row, c0), srcB2 + (size_t)row * PP + kt + c0 * 8);
            }
        } else if (MODE == 1) {
            int m = kt >> 7, cp0 = kt & 127;
#pragma unroll
            for (int u = 0; u < 2; u++) {
                int v = tid + u * 256;
                int r = v >> 4, ck = v & 15;
                int hc = ck >> 3, w8 = ck & 7;
                int cp = cp0 + r;
                int hp = h0 + 3 * m - 3 + hc;
                int valid = (hp >= 0 && hp < 64);
                int hpc = valid ? hp : 0;
                size_t s = (size_t)(nb * CH + cp) * PP + hpc * 64 + w8 * 8;
                cp16z(sb + A_BYTES + bswz(r, ck), g_t5s + s, valid ? 16 : 0);
            }
        } else {
            const __half* sB = (MODE == 0) ? g_t1s : g_t12s;
#pragma unroll
            for (int q = 0; q < 2; q++) {
                int c = tid + q * 256;
                int row = c >> 4, cb = c & 15;
                size_t gidx = ((size_t)nb * K3 + kt + row) * PP + nt0 + cb * 8;
                cp16(sb + A_BYTES + bswz(row, cb), sB + gidx);
            }
        }
    };

    auto compute = [&](int buf) {
        const unsigned sb = sm0 + buf * STG_BYTES;
#pragma unroll
        for (int ks = 0; ks < 2; ks++) {
            unsigned bh[4][2];
            if (MODE == 2) {
                int c0 = ((lane >> 3) & 1) + ks * 2;
#pragma unroll
                for (int q = 0; q < 2; q++) {
                    int nrow = wn + q * 16 + (lane & 7) + ((lane >> 4) & 1) * 8;
                    unsigned a = sb + A_BYTES + aswz(nrow, c0);
                    ldsm4(bh[2 * q][0], bh[2 * q][1], bh[2 * q + 1][0], bh[2 * q + 1][1], a);
                }
            } else {
                int row = ks * 16 + lr;
#pragma unroll
                for (int q = 0; q < 2; q++) {
                    int cb = (wn >> 3) + q * 2 + (lane >> 4);
                    unsigned a = sb + A_BYTES + bswz(row, cb);
                    ldsm4t(bh[2 * q][0], bh[2 * q][1], bh[2 * q + 1][0], bh[2 * q + 1][1], a);
                }
            }
            int ac0 = (lane >> 4) + ks * 2;
#pragma unroll
            for (int mt = 0; mt < 4; mt++) {
                unsigned aA = sb + aswz(wm + mt * 16 + lr, ac0);
                unsigned a0, a1, a2, a3;
                ldsm4(a0, a1, a2, a3, aA);
#pragma unroll
                for (int nt = 0; nt < 4; nt++) {
                    float* a = acc[mt][nt];
                    mma_f16(a[0], a[1], a[2], a[3], a0, a1, a2, a3, bh[nt][0], bh[nt][1]);
                }
            }
        }
    };

    const int nstages = KTOT / 32;
    // prologue: fill pipeline
#pragma unroll
    for (int s = 0; s < NSTG; s++) {
        if (s < nstages) {
            issue_stage(s * 32, s);
            asm volatile("cp.async.commit_group;");
        }
    }
    int buf = 0;
    for (int it = 0; it < nstages; ++it) {
        int rem = nstages - 1 - it;            // groups that must remain pending
        if (rem >= 3)      asm volatile("cp.async.wait_group 3;");
        else if (rem == 2) asm volatile("cp.async.wait_group 2;");
        else if (rem == 1) asm volatile("cp.async.wait_group 1;");
        else               asm volatile("cp.async.wait_group 0;");
        __syncthreads();
        compute(buf);
        __syncthreads();
        if (it + NSTG < nstages) {
            issue_stage((it + NSTG) * 32, buf);
            asm volatile("cp.async.commit_group;");
        }
        buf = (buf + 1 == NSTG) ? 0 : buf + 1;
    }

    const float scale = (MODE == 3) ? 0.051031036307982884f : 1.0f;
#pragma unroll
    for (int mt = 0; mt < 4; mt++) {
#pragma unroll
        for (int nt = 0; nt < 4; nt++) {
            int m0 = wm + mt * 16 + gq;
            int m1 = m0 + 8;
            int col = wn + nt * 8 + 2 * cq;
            float2 v0 = make_float2(acc[mt][nt][0] * scale, acc[mt][nt][1] * scale);
            float2 v1 = make_float2(acc[mt][nt][2] * scale, acc[mt][nt][3] * scale);
            if (MODE == 2) {
                float* cb = g_t9p + ((size_t)blockIdx.z * NB + nb) * CH * K3 + nt0;
                *reinterpret_cast<float2*>(&cb[(size_t)m0 * K3 + col]) = v0;
                *reinterpret_cast<float2*>(&cb[(size_t)m1 * K3 + col]) = v1;
            } else if (MODE == 3) {
                float* cb = Cdst + (size_t)nb * CH * PP + nt0;
                *reinterpret_cast<float2*>(&cb[(size_t)m0 * PP + col]) = v0;
                *reinterpret_cast<float2*>(&cb[(size_t)m1 * PP + col]) = v1;
            } else {
                size_t i0 = ((size_t)nb * CH + m0) * PP + nt0 + col;
                size_t i1 = ((size_t)nb * CH + m1) * PP + nt0 + col;
                if (MODE == 0) {
                    *reinterpret_cast<unsigned*>(&g_t3s[i0]) = pack2h(v0.x, v0.y);
                    *reinterpret_cast<unsigned*>(&g_t3s[i1]) = pack2h(v1.x, v1.y);
                } else {
                    *reinterpret_cast<unsigned*>(&g_t6s[i0]) = pack2h(v0.x, v0.y);
                    *reinterpret_cast<unsigned*>(&g_t6s[i1]) = pack2h(v1.x, v1.y);
                    float s0 = p8[m0], s1 = p8[m1];
                    *reinterpret_cast<unsigned*>(&g_t7s[i0]) =
                        pack2h(s0 * fmaxf(x[i0], v0.x), s0 * fmaxf(x[i0 + 1], v0.y));
                    *reinterpret_cast<unsigned*>(&g_t7s[i1]) =
                        pack2h(s1 * fmaxf(x[i1], v1.x), s1 * fmaxf(x[i1 + 1], v1.y));
                }
            }
        }
    }
}

// ---------------------------------------------------------------------------
extern "C" void kernel_launch(void* const* d_in, const int* in_sizes, int n_in,
                              void* d_out, int out_size)
{
    const float* x   = (const float*)d_in[0];
    const float* w3  = (const float*)d_in[1];
    const float* p5  = (const float*)d_in[2];
    const float* w6  = (const float*)d_in[3];
    const float* p8  = (const float*)d_in[4];
    const float* p12 = (const float*)d_in[5];
    float* out = (float*)d_out;

    const int SMB = NSTG * STG_BYTES;   // 65536 B
    cudaFuncSetAttribute(mma_gemm_kernel<0>, cudaFuncAttributeMaxDynamicSharedMemorySize, SMB);
    cudaFuncSetAttribute(mma_gemm_kernel<1>, cudaFuncAttributeMaxDynamicSharedMemorySize, SMB);
    cudaFuncSetAttribute(mma_gemm_kernel<2>, cudaFuncAttributeMaxDynamicSharedMemorySize, SMB);
    cudaFuncSetAttribute(mma_gemm_kernel<3>, cudaFuncAttributeMaxDynamicSharedMemorySize, SMB);

    prep_w_kernel<<<(CH * K3) / 256, 256>>>(w3, w6);
    prep_t1m_kernel<<<(NB * K3 * PP / 2) / 256, 256>>>(x);
    prep_t5_kernel<<<(NB * CH * PP / 2) / 256, 256>>>(x, p5);
    mma_gemm_kernel<0><<<dim3(32, NB), 256, SMB>>>(x, p8, nullptr);        // t3
    mma_gemm_kernel<1><<<dim3(32, NB), 256, SMB>>>(x, p8, nullptr);        // t6 + t7
    mma_gemm_kernel<2><<<dim3(3, NB, SPLITS), 256, SMB>>>(x, p8, nullptr); // t9 partials
    reduce_t9s_kernel<<<(NB * CH * K3 / 2) / 256, 256>>>();
    prep_t12_kernel<<<(NB * K3 * PP / 2) / 256, 256>>>(x, p12);
    mma_gemm_kernel<3><<<dim3(32, NB), 256, SMB>>>(x, p8, out);            // out
}

// round 14
// speedup vs baseline: 1.0143x; 1.0143x over previous
#include <cuda_runtime.h>
#include <cuda_fp16.h>
#include <cstdint>

#define NB 32
#define CH 128
#define PP 4096        // H*W
#define K3 384         // 3*C  (k' = m*128 + cp m-major order everywhere)
#define SPLITS 4       // split-K for t9 (over p)
#define NSTG 4         // cp.async pipeline depth

// swizzled smem tile sizes (bytes)
#define A_BYTES 8192
#define B_BYTES 8192
#define STG_BYTES (A_BYTES + B_BYTES)   // 16384

// fp32 scratch (split-K partials only)
__device__ float g_t9p[SPLITS * NB * CH * K3];
// fp16 operands
__device__ __half g_xh [NB * CH * PP];   // fp16 copy of x
__device__ __half g_w3r[CH * K3];
__device__ __half g_w6r[CH * K3];
__device__ __half g_t1s[NB * K3 * PP];   // t1m [nb][k'][p]
__device__ __half g_t5s[NB * CH * PP];
__device__ __half g_t3s[NB * CH * PP];
__device__ __half g_t6s[NB * CH * PP];
__device__ __half g_t7s[NB * CH * PP];
__device__ __half g_t12s[NB * K3 * PP];  // rows k'
__device__ __half g_t9s [NB * CH * K3]; // cols k'

// ---------------------------------------------------------------------------
__device__ __forceinline__ unsigned pack2h(float v0, float v1)
{
    __half2 hh = __halves2half2(__float2half(v0), __float2half(v1));
    return *reinterpret_cast<unsigned*>(&hh);
}

__device__ __forceinline__ void mma_f16(float& d0, float& d1, float& d2, float& d3,
                                        unsigned a0, unsigned a1, unsigned a2, unsigned a3,
                                        unsigned b0, unsigned b1)
{
    asm volatile(
        "mma.sync.aligned.m16n8k16.row.col.f32.f16.f16.f32 "
        "{%0,%1,%2,%3},{%4,%5,%6,%7},{%8,%9},{%0,%1,%2,%3};\n"
        : "+f"(d0), "+f"(d1), "+f"(d2), "+f"(d3)
        : "r"(a0), "r"(a1), "r"(a2), "r"(a3), "r"(b0), "r"(b1));
}

__device__ __forceinline__ void ldsm4(unsigned& r0, unsigned& r1, unsigned& r2, unsigned& r3, unsigned a)
{
    asm volatile("ldmatrix.sync.aligned.m8n8.x4.shared.b16 {%0,%1,%2,%3},[%4];"
                 : "=r"(r0), "=r"(r1), "=r"(r2), "=r"(r3) : "r"(a));
}
__device__ __forceinline__ void ldsm4t(unsigned& r0, unsigned& r1, unsigned& r2, unsigned& r3, unsigned a)
{
    asm volatile("ldmatrix.sync.aligned.m8n8.x4.trans.shared.b16 {%0,%1,%2,%3},[%4];"
                 : "=r"(r0), "=r"(r1), "=r"(r2), "=r"(r3) : "r"(a));
}
__device__ __forceinline__ void cp16(unsigned d, const void* s)
{
    asm volatile("cp.async.ca.shared.global [%0], [%1], 16;" :: "r"(d), "l"(s));
}
__device__ __forceinline__ void cp16z(unsigned d, const void* s, int sz)
{
    asm volatile("cp.async.ca.shared.global [%0], [%1], 16, %2;" :: "r"(d), "l"(s), "r"(sz));
}

// A-style tile: 128 rows x 32 halfs (64B); 2 rows per 128B line.
__device__ __forceinline__ int aswz(int row, int c0)
{
    return (row >> 1) * 128 + (((((row & 1) << 2) | c0) ^ ((row >> 1) & 7)) << 4);
}
// B [k][n] tile: 32 rows x 128 halfs (256B rows, 16 chunks).
__device__ __forceinline__ int bswz(int row, int cb)
{
    return row * 256 + ((cb ^ (row & 7)) << 4);
}

// ---------------------------------------------------------------------------
// Prep kernels
// ---------------------------------------------------------------------------
__global__ void prep_w_kernel(const float* __restrict__ w3, const float* __restrict__ w6)
{
    int idx = blockIdx.x * 256 + threadIdx.x;
    int half_n = CH * K3 / 2;
    const float* src = (idx < half_n) ? w3 : w6;
    __half* dh = (idx < half_n) ? g_w3r : g_w6r;
    int i2 = (idx % half_n) * 2;
    int o = i2 / K3;
    int kp = i2 - o * K3;
    int m = kp >> 7;
    int cp = kp & 127;
    *reinterpret_cast<unsigned*>(&dh[i2]) =
        pack2h(src[o * K3 + 3 * cp + m], src[o * K3 + 3 * (cp + 1) + m]);
}

// ONE pass over fp32 x: writes xh (fp16 copy) AND t5 = p5 * max3_w(x)
__global__ void prep_xt5_kernel(const float* __restrict__ x, const float* __restrict__ p5)
{
    int i2 = (blockIdx.x * 256 + threadIdx.x) * 2;
    if (i2 >= NB * CH * PP) return;
    int p = i2 & (PP - 1);
    int w = p & 63;
    const float* xr = x + (i2 - w);
    float x0 = xr[w], x1 = xr[w + 1];
    *reinterpret_cast<unsigned*>(&g_xh[i2]) = pack2h(x0, x1);
    float v[2];
#pragma unroll
    for (int e = 0; e < 2; e++) {
        int we = w + e;
        float mx = (e == 0) ? x0 : x1;
        if (we >= 2) mx = fmaxf(mx, xr[we - 2]);
        if (we < 62) mx = fmaxf(mx, xr[we + 2]);
        v[e] = p5[p - w + we] * mx;
    }
    *reinterpret_cast<unsigned*>(&g_t5s[i2]) = pack2h(v[0], v[1]);
}

// t1m[nb][k'=m*128+cp][p] = xh[nb][cp][p + 2m-2] (zero pad in w)
__global__ void prep_t1m_kernel()
{
    int i2 = (blockIdx.x * 256 + threadIdx.x) * 2;
    int p = i2 & (PP - 1);
    int r = i2 >> 12;
    int kp = r % K3;
    int nb = r / K3;
    int m = kp >> 7, cp = kp & 127;
    int w = p & 63;
    const __half* xr = g_xh + (size_t)(nb * CH + cp) * PP + (p - w);
    int sh = 2 * m - 2;
    __half z = __float2half(0.f);
    __half v0 = ((unsigned)(w + sh)     < 64u) ? xr[w + sh]     : z;
    __half v1 = ((unsigned)(w + 1 + sh) < 64u) ? xr[w + 1 + sh] : z;
    __half2 hh = __halves2half2(v0, v1);
    *reinterpret_cast<unsigned*>(&g_t1s[i2]) = *reinterpret_cast<unsigned*>(&hh);
}

// t12[nb][k'=j*128+cp][p] = p12[j,h] * max(t6, max(x,t6) + max(t3, t1_j))
__global__ void prep_t12_kernel(const float* __restrict__ p12)
{
    int i2 = (blockIdx.x * 256 + threadIdx.x) * 2;
    int p = i2 & (PP - 1);
    int r = i2 >> 12;
    int kp = r % K3;
    int nb = r / K3;
    int j  = kp >> 7;
    int cp = kp & 127;
    int h = p >> 6;
    int w = p & 63;
    size_t base = ((size_t)nb * CH + cp) * PP + p;
    float sc = p12[j * 64 + h];
    float2 fx = __half22float2(*reinterpret_cast<const __half2*>(&g_xh[base]));
    float2 f6 = __half22float2(*reinterpret_cast<const __half2*>(&g_t6s[base]));
    float2 f3 = __half22float2(*reinterpret_cast<const __half2*>(&g_t3s[base]));
    const __half* xr = g_xh + base - w;
    float v[2];
#pragma unroll
    for (int e = 0; e < 2; e++) {
        float xv  = (e == 0) ? fx.x : fx.y;
        float t6v = (e == 0) ? f6.x : f6.y;
        float t3v = (e == 0) ? f3.x : f3.y;
        int wq = w + e + 2 * j - 2;
        float x1 = ((unsigned)wq < 64u) ? __half2float(xr[wq]) : 0.f;
        v[e] = sc * fmaxf(t6v, fmaxf(xv, t6v) + fmaxf(t3v, x1));
    }
    *reinterpret_cast<unsigned*>(&g_t12s[i2]) = pack2h(v[0], v[1]);
}

__global__ void reduce_t9s_kernel()
{
    int i2 = (blockIdx.x * 256 + threadIdx.x) * 2;
    float s0 = 0.f, s1 = 0.f;
#pragma unroll
    for (int u = 0; u < SPLITS; u++) {
        s0 += g_t9p[(size_t)u * NB * CH * K3 + i2];
        s1 += g_t9p[(size_t)u * NB * CH * K3 + i2 + 1];
    }
    *reinterpret_cast<unsigned*>(&g_t9s[i2]) =
        pack2h(s0 * (1.0f / 64.0f), s1 * (1.0f / 64.0f));
}

// ---------------------------------------------------------------------------
// mma.sync GEMM — 256 threads (8 warps 2m x 4n, warp tile 64x32), 1 MMA,
// 4-stage cp.async pipeline, XOR-swizzled smem.
//   MODE 0: t3  = w3r @ t1s        K=384   -> g_t3s (fp16)
//   MODE 1: t6  = w6r @ t5s(hsh)   K=384   -> g_t6s + fused t7 epilogue
//   MODE 2: t9p = t7s @ t1s^T      K=1024 slab -> g_t9p (fp32)
//   MODE 3: out = t9s @ t12s       K=384   -> out (fp32, scaled)
// ---------------------------------------------------------------------------
template <int MODE>
__global__ void __launch_bounds__(256, 2)
mma_gemm_kernel(const float* __restrict__ p8, float* __restrict__ Cdst)
{
    extern __shared__ __half smbuf[];
    const int KTOT    = (MODE == 2) ? (PP / SPLITS) : K3;
    const int nb      = blockIdx.y;
    const int nt0     = blockIdx.x * 128;
    const int kbase   = (MODE == 2) ? blockIdx.z * (PP / SPLITS) : 0;

    const int tid = threadIdx.x;
    const int wid = tid >> 5, lane = tid & 31;
    const int gq = lane >> 2, cq = lane & 3;
    const int lr = lane & 15;
    const int wm = (wid >> 2) * 64, wn = (wid & 3) * 32;
    const int h0 = nt0 >> 6;

    const unsigned sm0 = (unsigned)__cvta_generic_to_shared(smbuf);

    const __half *srcA;
    int strideA;
    if (MODE == 0)      { srcA = g_w3r; strideA = K3; }
    else if (MODE == 1) { srcA = g_w6r; strideA = K3; }
    else if (MODE == 2) { srcA = g_t7s + (size_t)nb * CH * PP + kbase; strideA = PP; }
    else                { srcA = g_t9s + (size_t)nb * CH * K3; strideA = K3; }

    const __half* srcB2 = g_t1s + ((size_t)nb * K3 + nt0) * PP + kbase;

    float acc[4][4][4];
#pragma unroll
    for (int i = 0; i < 4; i++)
#pragma unroll
        for (int j = 0; j < 4; j++)
#pragma unroll
            for (int q = 0; q < 4; q++) acc[i][j][q] = 0.f;

    auto issue_stage = [&](int kt, int buf) {
        const unsigned sb = sm0 + buf * STG_BYTES;
#pragma unroll
        for (int q = 0; q < 2; q++) {
            int c = tid + q * 256;
            int row = c >> 2, c0 = c & 3;
            cp16(sb + aswz(row, c0), srcA + (size_t)row * strideA + kt + c0 * 8);
        }
        if (MODE == 2) {
#pragma unroll
            for (int q = 0; q < 2; q++) {
                int c = tid + q * 256;
                int row = c >> 2, c0 = c & 3;
                cp16(sb + A_BYTES + aswz(row, c0), srcB2 + (size_t)row * PP + kt + c0 * 8);
            }
        } else if (MODE == 1) {
            int m = kt >> 7, cp0 = kt & 127;
#pragma unroll
            for (int u = 0; u < 2; u++) {
                int v = tid + u * 256;
                int r = v >> 4, ck = v & 15;
                int hc = ck >> 3, w8 = ck & 7;
                int cp = cp0 + r;
                int hp = h0 + 3 * m - 3 + hc;
                int valid = (hp >= 0 && hp < 64);
                int hpc = valid ? hp : 0;
                size_t s = (size_t)(nb * CH + cp) * PP + hpc * 64 + w8 * 8;
                cp16z(sb + A_BYTES + bswz(r, ck), g_t5s + s, valid ? 16 : 0);
            }
        } else {
            const __half* sB = (MODE == 0) ? g_t1s : g_t12s;
#pragma unroll
            for (int q = 0; q < 2; q++) {
                int c = tid + q * 256;
                int row = c >> 4, cb = c & 15;
                size_t gidx = ((size_t)nb * K3 + kt + row) * PP + nt0 + cb * 8;
                cp16(sb + A_BYTES + bswz(row, cb), sB + gidx);
            }
        }
    };

    auto compute = [&](int buf) {
        const unsigned sb = sm0 + buf * STG_BYTES;
#pragma unroll
        for (int ks = 0; ks < 2; ks++) {
            unsigned bh[4][2];
            if (MODE == 2) {
                int c0 = ((lane >> 3) & 1) + ks * 2;
#pragma unroll
                for (int q = 0; q < 2; q++) {
                    int nrow = wn + q * 16 + (lane & 7) + ((lane >> 4) & 1) * 8;
                    unsigned a = sb + A_BYTES + aswz(nrow, c0);
                    ldsm4(bh[2 * q][0], bh[2 * q][1], bh[2 * q + 1][0], bh[2 * q + 1][1], a);
                }
            } else {
                int row = ks * 16 + lr;
#pragma unroll
                for (int q = 0; q < 2; q++) {
                    int cb = (wn >> 3) + q * 2 + (lane >> 4);
                    unsigned a = sb + A_BYTES + bswz(row, cb);
                    ldsm4t(bh[2 * q][0], bh[2 * q][1], bh[2 * q + 1][0], bh[2 * q + 1][1], a);
                }
            }
            int ac0 = (lane >> 4) + ks * 2;
#pragma unroll
            for (int mt = 0; mt < 4; mt++) {
                unsigned aA = sb + aswz(wm + mt * 16 + lr, ac0);
                unsigned a0, a1, a2, a3;
                ldsm4(a0, a1, a2, a3, aA);
#pragma unroll
                for (int nt = 0; nt < 4; nt++) {
                    float* a = acc[mt][nt];
                    mma_f16(a[0], a[1], a[2], a[3], a0, a1, a2, a3, bh[nt][0], bh[nt][1]);
                }
            }
        }
    };

    const int nstages = KTOT / 32;
#pragma unroll
    for (int s = 0; s < NSTG; s++) {
        if (s < nstages) {
            issue_stage(s * 32, s);
            asm volatile("cp.async.commit_group;");
        }
    }
    int buf = 0;
    for (int it = 0; it < nstages; ++it) {
        int rem = nstages - 1 - it;
        if (rem >= 3)      asm volatile("cp.async.wait_group 3;");
        else if (rem == 2) asm volatile("cp.async.wait_group 2;");
        else if (rem == 1) asm volatile("cp.async.wait_group 1;");
        else               asm volatile("cp.async.wait_group 0;");
        __syncthreads();
        compute(buf);
        __syncthreads();
        if (it + NSTG < nstages) {
            issue_stage((it + NSTG) * 32, buf);
            asm volatile("cp.async.commit_group;");
        }
        buf = (buf + 1 == NSTG) ? 0 : buf + 1;
    }

    const float scale = (MODE == 3) ? 0.051031036307982884f : 1.0f;
#pragma unroll
    for (int mt = 0; mt < 4; mt++) {
#pragma unroll
        for (int nt = 0; nt < 4; nt++) {
            int m0 = wm + mt * 16 + gq;
            int m1 = m0 + 8;
            int col = wn + nt * 8 + 2 * cq;
            float2 v0 = make_float2(acc[mt][nt][0] * scale, acc[mt][nt][1] * scale);
            float2 v1 = make_float2(acc[mt][nt][2] * scale, acc[mt][nt][3] * scale);
            if (MODE == 2) {
                float* cb = g_t9p + ((size_t)blockIdx.z * NB + nb) * CH * K3 + nt0;
                *reinterpret_cast<float2*>(&cb[(size_t)m0 * K3 + col]) = v0;
                *reinterpret_cast<float2*>(&cb[(size_t)m1 * K3 + col]) = v1;
            } else if (MODE == 3) {
                float* cb = Cdst + (size_t)nb * CH * PP + nt0;
                *reinterpret_cast<float2*>(&cb[(size_t)m0 * PP + col]) = v0;
                *reinterpret_cast<float2*>(&cb[(size_t)m1 * PP + col]) = v1;
            } else {
                size_t i0 = ((size_t)nb * CH + m0) * PP + nt0 + col;
                size_t i1 = ((size_t)nb * CH + m1) * PP + nt0 + col;
                if (MODE == 0) {
                    *reinterpret_cast<unsigned*>(&g_t3s[i0]) = pack2h(v0.x, v0.y);
                    *reinterpret_cast<unsigned*>(&g_t3s[i1]) = pack2h(v1.x, v1.y);
                } else {
                    *reinterpret_cast<unsigned*>(&g_t6s[i0]) = pack2h(v0.x, v0.y);
                    *reinterpret_cast<unsigned*>(&g_t6s[i1]) = pack2h(v1.x, v1.y);
                    float2 fx0 = __half22float2(*reinterpret_cast<const __half2*>(&g_xh[i0]));
                    float2 fx1 = __half22float2(*reinterpret_cast<const __half2*>(&g_xh[i1]));
                    float s0 = p8[m0], s1 = p8[m1];
                    *reinterpret_cast<unsigned*>(&g_t7s[i0]) =
                        pack2h(s0 * fmaxf(fx0.x, v0.x), s0 * fmaxf(fx0.y, v0.y));
                    *reinterpret_cast<unsigned*>(&g_t7s[i1]) =
                        pack2h(s1 * fmaxf(fx1.x, v1.x), s1 * fmaxf(fx1.y, v1.y));
                }
            }
        }
    }
}

// ---------------------------------------------------------------------------
extern "C" void kernel_launch(void* const* d_in, const int* in_sizes, int n_in,
                              void* d_out, int out_size)
{
    const float* x   = (const float*)d_in[0];
    const float* w3  = (const float*)d_in[1];
    const float* p5  = (const float*)d_in[2];
    const float* w6  = (const float*)d_in[3];
    const float* p8  = (const float*)d_in[4];
    const float* p12 = (const float*)d_in[5];
    float* out = (float*)d_out;

    const int SMB = NSTG * STG_BYTES;   // 65536 B
    cudaFuncSetAttribute(mma_gemm_kernel<0>, cudaFuncAttributeMaxDynamicSharedMemorySize, SMB);
    cudaFuncSetAttribute(mma_gemm_kernel<1>, cudaFuncAttributeMaxDynamicSharedMemorySize, SMB);
    cudaFuncSetAttribute(mma_gemm_kernel<2>, cudaFuncAttributeMaxDynamicSharedMemorySize, SMB);
    cudaFuncSetAttribute(mma_gemm_kernel<3>, cudaFuncAttributeMaxDynamicSharedMemorySize, SMB);

    prep_w_kernel<<<(CH * K3) / 256, 256>>>(w3, w6);
    prep_xt5_kernel<<<(NB * CH * PP / 2) / 256, 256>>>(x, p5);   // xh + t5
    prep_t1m_kernel<<<(NB * K3 * PP / 2) / 256, 256>>>();        // t1m from xh
    mma_gemm_kernel<0><<<dim3(32, NB), 256, SMB>>>(p8, nullptr);        // t3
    mma_gemm_kernel<1><<<dim3(32, NB), 256, SMB>>>(p8, nullptr);        // t6 + t7
    mma_gemm_kernel<2><<<dim3(3, NB, SPLITS), 256, SMB>>>(p8, nullptr); // t9 partials
    reduce_t9s_kernel<<<(NB * CH * K3 / 2) / 256, 256>>>();
    prep_t12_kernel<<<(NB * K3 * PP / 2) / 256, 256>>>(p12);            // t12 from xh
    mma_gemm_kernel<3><<<dim3(32, NB), 256, SMB>>>(p8, out);            // out
}

// round 15
// speedup vs baseline: 1.1217x; 1.1059x over previous
#include <cuda_runtime.h>
#include <cuda_fp16.h>
#include <cstdint>

#define NB 32
#define CH 128
#define PP 4096        // H*W
#define K3 384         // 3*C  (k' = m*128 + cp m-major order everywhere)
#define SPLITS 4       // split-K for t9 (over p)
#define NSTG 4         // cp.async pipeline depth

// swizzled smem tile sizes (bytes)
#define A_BYTES 8192
#define B_BYTES 8192
#define STG_BYTES (A_BYTES + B_BYTES)   // 16384

// fp32 scratch (split-K partials only)
__device__ float g_t9p[SPLITS * NB * CH * K3];
// fp16 operands
__device__ __half g_xh  [NB * CH * PP];       // fp16 copy of x  (== t1 m=1 plane)
__device__ __half g_w3r [CH * K3];
__device__ __half g_w6r [CH * K3];
__device__ __half g_t1s2[NB * 2 * CH * PP];   // t1 planes m=0 (sh=-2), m=2 (sh=+2)
__device__ __half g_t5s [NB * CH * PP];
__device__ __half g_t3s [NB * CH * PP];
__device__ __half g_t6s [NB * CH * PP];
__device__ __half g_t7s [NB * CH * PP];
__device__ __half g_t9s [NB * CH * K3];

// ---------------------------------------------------------------------------
__device__ __forceinline__ unsigned pack2h(float v0, float v1)
{
    __half2 hh = __halves2half2(__float2half(v0), __float2half(v1));
    return *reinterpret_cast<unsigned*>(&hh);
}

__device__ __forceinline__ void mma_f16(float& d0, float& d1, float& d2, float& d3,
                                        unsigned a0, unsigned a1, unsigned a2, unsigned a3,
                                        unsigned b0, unsigned b1)
{
    asm volatile(
        "mma.sync.aligned.m16n8k16.row.col.f32.f16.f16.f32 "
        "{%0,%1,%2,%3},{%4,%5,%6,%7},{%8,%9},{%0,%1,%2,%3};\n"
        : "+f"(d0), "+f"(d1), "+f"(d2), "+f"(d3)
        : "r"(a0), "r"(a1), "r"(a2), "r"(a3), "r"(b0), "r"(b1));
}

__device__ __forceinline__ void ldsm4(unsigned& r0, unsigned& r1, unsigned& r2, unsigned& r3, unsigned a)
{
    asm volatile("ldmatrix.sync.aligned.m8n8.x4.shared.b16 {%0,%1,%2,%3},[%4];"
                 : "=r"(r0), "=r"(r1), "=r"(r2), "=r"(r3) : "r"(a));
}
__device__ __forceinline__ void ldsm4t(unsigned& r0, unsigned& r1, unsigned& r2, unsigned& r3, unsigned a)
{
    asm volatile("ldmatrix.sync.aligned.m8n8.x4.trans.shared.b16 {%0,%1,%2,%3},[%4];"
                 : "=r"(r0), "=r"(r1), "=r"(r2), "=r"(r3) : "r"(a));
}
__device__ __forceinline__ void cp16(unsigned d, const void* s)
{
    asm volatile("cp.async.ca.shared.global [%0], [%1], 16;" :: "r"(d), "l"(s));
}
__device__ __forceinline__ void cp16z(unsigned d, const void* s, int sz)
{
    asm volatile("cp.async.ca.shared.global [%0], [%1], 16, %2;" :: "r"(d), "l"(s), "r"(sz));
}

// A-style tile: 128 rows x 32 halfs (64B); 2 rows per 128B line.
__device__ __forceinline__ int aswz(int row, int c0)
{
    return (row >> 1) * 128 + (((((row & 1) << 2) | c0) ^ ((row >> 1) & 7)) << 4);
}
// B [k][n] tile: 32 rows x 128 halfs (256B rows, 16 chunks).
__device__ __forceinline__ int bswz(int row, int cb)
{
    return row * 256 + ((cb ^ (row & 7)) << 4);
}

// ---------------------------------------------------------------------------
// Prep kernels
// ---------------------------------------------------------------------------
__global__ void prep_w_kernel(const float* __restrict__ w3, const float* __restrict__ w6)
{
    int idx = blockIdx.x * 256 + threadIdx.x;
    int half_n = CH * K3 / 2;
    const float* src = (idx < half_n) ? w3 : w6;
    __half* dh = (idx < half_n) ? g_w3r : g_w6r;
    int i2 = (idx % half_n) * 2;
    int o = i2 / K3;
    int kp = i2 - o * K3;
    int m = kp >> 7;
    int cp = kp & 127;
    *reinterpret_cast<unsigned*>(&dh[i2]) =
        pack2h(src[o * K3 + 3 * cp + m], src[o * K3 + 3 * (cp + 1) + m]);
}

// ONE pass over fp32 x: writes xh (fp16 copy) AND t5 = p5 * max3_w(x)
__global__ void prep_xt5_kernel(const float* __restrict__ x, const float* __restrict__ p5)
{
    int i2 = (blockIdx.x * 256 + threadIdx.x) * 2;
    if (i2 >= NB * CH * PP) return;
    int p = i2 & (PP - 1);
    int w = p & 63;
    const float* xr = x + (i2 - w);
    float x0 = xr[w], x1 = xr[w + 1];
    *reinterpret_cast<unsigned*>(&g_xh[i2]) = pack2h(x0, x1);
    float v[2];
#pragma unroll
    for (int e = 0; e < 2; e++) {
        int we = w + e;
        float mx = (e == 0) ? x0 : x1;
        if (we >= 2) mx = fmaxf(mx, xr[we - 2]);
        if (we < 62) mx = fmaxf(mx, xr[we + 2]);
        v[e] = p5[p - w + we] * mx;
    }
    *reinterpret_cast<unsigned*>(&g_t5s[i2]) = pack2h(v[0], v[1]);
}

// t1s2[nb][mi][cp][p] = xh[nb][cp][p + (mi? +2 : -2)] (zero pad in w)
__global__ void prep_t1m_kernel()
{
    int i2 = (blockIdx.x * 256 + threadIdx.x) * 2;
    int p = i2 & (PP - 1);
    int rr = i2 >> 12;               // [nb][mi][cp]
    int cp = rr & 127;
    int mi = (rr >> 7) & 1;
    int nb = rr >> 8;
    int w = p & 63;
    const __half* xr = g_xh + (size_t)(nb * CH + cp) * PP + (p - w);
    int sh = mi ? 2 : -2;
    __half z = __float2half(0.f);
    __half v0 = ((unsigned)(w + sh)     < 64u) ? xr[w + sh]     : z;
    __half v1 = ((unsigned)(w + 1 + sh) < 64u) ? xr[w + 1 + sh] : z;
    __half2 hh = __halves2half2(v0, v1);
    *reinterpret_cast<unsigned*>(&g_t1s2[i2]) = *reinterpret_cast<unsigned*>(&hh);
}

__global__ void reduce_t9s_kernel()
{
    int i2 = (blockIdx.x * 256 + threadIdx.x) * 2;
    float s0 = 0.f, s1 = 0.f;
#pragma unroll
    for (int u = 0; u < SPLITS; u++) {
        s0 += g_t9p[(size_t)u * NB * CH * K3 + i2];
        s1 += g_t9p[(size_t)u * NB * CH * K3 + i2 + 1];
    }
    *reinterpret_cast<unsigned*>(&g_t9s[i2]) =
        pack2h(s0 * (1.0f / 64.0f), s1 * (1.0f / 64.0f));
}

// selects the t1 plane for a given m (0/1/2)
__device__ __forceinline__ const __half* t1_base(int nb, int m)
{
    if (m == 1) return g_xh + (size_t)nb * CH * PP;
    return g_t1s2 + ((size_t)(nb * 2 + (m >> 1)) * CH) * PP;
}

// ---------------------------------------------------------------------------
// mma.sync GEMM — 256 threads (8 warps 2m x 4n, warp tile 64x32), 1 MMA,
// 4-stage cp.async pipeline, XOR-swizzled smem.
//   MODE 0: t3  = w3r @ t1         K=384   -> g_t3s (fp16)
//   MODE 1: t6  = w6r @ t5s(hsh)   K=384   -> g_t6s + fused t7 epilogue
//   MODE 2: t9p = t7s @ t1^T       K=1024 slab -> g_t9p (fp32)
// ---------------------------------------------------------------------------
template <int MODE>
__global__ void __launch_bounds__(256, 2)
mma_gemm_kernel(const float* __restrict__ p8)
{
    extern __shared__ __half smbuf[];
    const int KTOT    = (MODE == 2) ? (PP / SPLITS) : K3;
    const int nb      = blockIdx.y;
    const int nt0     = blockIdx.x * 128;
    const int kbase   = (MODE == 2) ? blockIdx.z * (PP / SPLITS) : 0;

    const int tid = threadIdx.x;
    const int wid = tid >> 5, lane = tid & 31;
    const int gq = lane >> 2, cq = lane & 3;
    const int lr = lane & 15;
    const int wm = (wid >> 2) * 64, wn = (wid & 3) * 32;
    const int h0 = nt0 >> 6;

    const unsigned sm0 = (unsigned)__cvta_generic_to_shared(smbuf);

    const __half *srcA;
    int strideA;
    if (MODE == 0)      { srcA = g_w3r; strideA = K3; }
    else if (MODE == 1) { srcA = g_w6r; strideA = K3; }
    else                { srcA = g_t7s + (size_t)nb * CH * PP + kbase; strideA = PP; }

    // MODE 2: B rows are j' = nt0 + row; one m per j-tile
    const __half* srcB2 = (MODE == 2) ? (t1_base(nb, nt0 >> 7) + kbase) : nullptr;

    float acc[4][4][4];
#pragma unroll
    for (int i = 0; i < 4; i++)
#pragma unroll
        for (int j = 0; j < 4; j++)
#pragma unroll
            for (int q = 0; q < 4; q++) acc[i][j][q] = 0.f;

    auto issue_stage = [&](int kt, int buf) {
        const unsigned sb = sm0 + buf * STG_BYTES;
#pragma unroll
        for (int q = 0; q < 2; q++) {
            int c = tid + q * 256;
            int row = c >> 2, c0 = c & 3;
            cp16(sb + aswz(row, c0), srcA + (size_t)row * strideA + kt + c0 * 8);
        }
        if (MODE == 2) {
#pragma unroll
            for (int q = 0; q < 2; q++) {
                int c = tid + q * 256;
                int row = c >> 2, c0 = c & 3;
                cp16(sb + A_BYTES + aswz(row, c0), srcB2 + (size_t)row * PP + kt + c0 * 8);
            }
        } else if (MODE == 1) {
            int m = kt >> 7, cp0 = kt & 127;
#pragma unroll
            for (int u = 0; u < 2; u++) {
                int v = tid + u * 256;
                int r = v >> 4, ck = v & 15;
                int hc = ck >> 3, w8 = ck & 7;
                int cp = cp0 + r;
                int hp = h0 + 3 * m - 3 + hc;
                int valid = (hp >= 0 && hp < 64);
                int hpc = valid ? hp : 0;
                size_t s = (size_t)(nb * CH + cp) * PP + hpc * 64 + w8 * 8;
                cp16z(sb + A_BYTES + bswz(r, ck), g_t5s + s, valid ? 16 : 0);
            }
        } else { // MODE 0: B = t1[k' slab][p-tile], one m per slab
            int m = kt >> 7, cp0 = kt & 127;
            const __half* base = t1_base(nb, m);
#pragma unroll
            for (int q = 0; q < 2; q++) {
                int c = tid + q * 256;
                int row = c >> 4, cb = c & 15;
                size_t gidx = (size_t)(cp0 + row) * PP + nt0 + cb * 8;
                cp16(sb + A_BYTES + bswz(row, cb), base + gidx);
            }
        }
    };

    auto compute = [&](int buf) {
        const unsigned sb = sm0 + buf * STG_BYTES;
#pragma unroll
        for (int ks = 0; ks < 2; ks++) {
            unsigned bh[4][2];
            if (MODE == 2) {
                int c0 = ((lane >> 3) & 1) + ks * 2;
#pragma unroll
                for (int q = 0; q < 2; q++) {
                    int nrow = wn + q * 16 + (lane & 7) + ((lane >> 4) & 1) * 8;
                    unsigned a = sb + A_BYTES + aswz(nrow, c0);
                    ldsm4(bh[2 * q][0], bh[2 * q][1], bh[2 * q + 1][0], bh[2 * q + 1][1], a);
                }
            } else {
                int row = ks * 16 + lr;
#pragma unroll
                for (int q = 0; q < 2; q++) {
                    int cb = (wn >> 3) + q * 2 + (lane >> 4);
                    unsigned a = sb + A_BYTES + bswz(row, cb);
                    ldsm4t(bh[2 * q][0], bh[2 * q][1], bh[2 * q + 1][0], bh[2 * q + 1][1], a);
                }
            }
            int ac0 = (lane >> 4) + ks * 2;
#pragma unroll
            for (int mt = 0; mt < 4; mt++) {
                unsigned aA = sb + aswz(wm + mt * 16 + lr, ac0);
                unsigned a0, a1, a2, a3;
                ldsm4(a0, a1, a2, a3, aA);
#pragma unroll
                for (int nt = 0; nt < 4; nt++) {
                    float* a = acc[mt][nt];
                    mma_f16(a[0], a[1], a[2], a[3], a0, a1, a2, a3, bh[nt][0], bh[nt][1]);
                }
            }
        }
    };

    const int nstages = KTOT / 32;
#pragma unroll
    for (int s = 0; s < NSTG; s++) {
        if (s < nstages) {
            issue_stage(s * 32, s);
            asm volatile("cp.async.commit_group;");
        }
    }
    int buf = 0;
    for (int it = 0; it < nstages; ++it) {
        int rem = nstages - 1 - it;
        if (rem >= 3)      asm volatile("cp.async.wait_group 3;");
        else if (rem == 2) asm volatile("cp.async.wait_group 2;");
        else if (rem == 1) asm volatile("cp.async.wait_group 1;");
        else               asm volatile("cp.async.wait_group 0;");
        __syncthreads();
        compute(buf);
        __syncthreads();
        if (it + NSTG < nstages) {
            issue_stage((it + NSTG) * 32, buf);
            asm volatile("cp.async.commit_group;");
        }
        buf = (buf + 1 == NSTG) ? 0 : buf + 1;
    }

    // epilogue
#pragma unroll
    for (int mt = 0; mt < 4; mt++) {
#pragma unroll
        for (int nt = 0; nt < 4; nt++) {
            int m0 = wm + mt * 16 + gq;
            int m1 = m0 + 8;
            int col = wn + nt * 8 + 2 * cq;
            float2 v0 = make_float2(acc[mt][nt][0], acc[mt][nt][1]);
            float2 v1 = make_float2(acc[mt][nt][2], acc[mt][nt][3]);
            if (MODE == 2) {
                float* cb = g_t9p + ((size_t)blockIdx.z * NB + nb) * CH * K3 + nt0;
                *reinterpret_cast<float2*>(&cb[(size_t)m0 * K3 + col]) = v0;
                *reinterpret_cast<float2*>(&cb[(size_t)m1 * K3 + col]) = v1;
            } else {
                size_t i0 = ((size_t)nb * CH + m0) * PP + nt0 + col;
                size_t i1 = ((size_t)nb * CH + m1) * PP + nt0 + col;
                if (MODE == 0) {
                    *reinterpret_cast<unsigned*>(&g_t3s[i0]) = pack2h(v0.x, v0.y);
                    *reinterpret_cast<unsigned*>(&g_t3s[i1]) = pack2h(v1.x, v1.y);
                } else {
                    *reinterpret_cast<unsigned*>(&g_t6s[i0]) = pack2h(v0.x, v0.y);
                    *reinterpret_cast<unsigned*>(&g_t6s[i1]) = pack2h(v1.x, v1.y);
                    float2 fx0 = __half22float2(*reinterpret_cast<const __half2*>(&g_xh[i0]));
                    float2 fx1 = __half22float2(*reinterpret_cast<const __half2*>(&g_xh[i1]));
                    float s0 = p8[m0], s1 = p8[m1];
                    *reinterpret_cast<unsigned*>(&g_t7s[i0]) =
                        pack2h(s0 * fmaxf(fx0.x, v0.x), s0 * fmaxf(fx0.y, v0.y));
                    *reinterpret_cast<unsigned*>(&g_t7s[i1]) =
                        pack2h(s1 * fmaxf(fx1.x, v1.x), s1 * fmaxf(fx1.y, v1.y));
                }
            }
        }
    }
}

// ---------------------------------------------------------------------------
// Fused output GEMM: out[c][p] = (1/sqrt(384)) * sum_k' t9[c][k'] * t12[k'][p]
// with t12 recomputed on the fly (never materialized):
//   t12[j*128+cp][p] = p12[j,h] * max(t6, max(x,t6) + max(t3, x_shift(2j-2)))
// K loop: cp-block outer (xh window staged once), j inner.
// ---------------------------------------------------------------------------
__global__ void __launch_bounds__(256, 2)
mma_out_kernel(const float* __restrict__ p12, float* __restrict__ out)
{
    __shared__ __align__(16) __half sA[4096];
    __shared__ __align__(16) __half sB[4096];
    __shared__ __align__(16) __half sX[32 * 144];   // xh window [nt0-8, nt0+136)

    const int nb  = blockIdx.y;
    const int nt0 = blockIdx.x * 128;
    const int h0  = nt0 >> 6;
    const int tid = threadIdx.x;
    const int wid = tid >> 5, lane = tid & 31;
    const int gq = lane >> 2, cq = lane & 3;
    const int lr = lane & 15;
    const int wm = (wid >> 2) * 64, wn = (wid & 3) * 32;

    const unsigned uA = (unsigned)__cvta_generic_to_shared(sA);
    const unsigned uB = (unsigned)__cvta_generic_to_shared(sB);
    const unsigned uX = (unsigned)__cvta_generic_to_shared(sX);

    const __half* xb  = g_xh  + (size_t)nb * CH * PP;
    const __half* t6b = g_t6s + (size_t)nb * CH * PP;
    const __half* t3b = g_t3s + (size_t)nb * CH * PP;
    const __half* t9b = g_t9s + (size_t)nb * CH * K3;

    float acc[4][4][4];
#pragma unroll
    for (int i = 0; i < 4; i++)
#pragma unroll
        for (int j = 0; j < 4; j++)
#pragma unroll
            for (int q = 0; q < 4; q++) acc[i][j][q] = 0.f;

    const int fr  = tid >> 3;           // fill row 0..31
    const int fc8 = (tid & 7) * 16;     // fill col base

    for (int cpb = 0; cpb < 4; cpb++) {
        const int cp0 = cpb * 32;
        // stage xh window (rows cp0..cp0+31, halo ±8 halfs)
#pragma unroll
        for (int q = 0; q < 3; q++) {
            int idx = tid + q * 256;
            if (idx < 576) {
                int row = idx / 18, ch = idx - row * 18;
                int p = nt0 - 8 + ch * 8;
                int valid = (p >= 0 && p + 8 <= PP);
                const __half* s = xb + (size_t)(cp0 + row) * PP + (valid ? p : 0);
                cp16z(uX + 2 * (row * 144 + ch * 8), s, valid ? 16 : 0);
            }
        }
        asm volatile("cp.async.commit_group;");

        for (int j = 0; j < 3; j++) {
            // A tile: 128 rows (c) x 32 k'  (k' = j*128 + cp0 ..)
            {
                int kc = j * 128 + cp0;
#pragma unroll
                for (int q = 0; q < 2; q++) {
                    int c = tid + q * 256;
                    int row = c >> 2, c0 = c & 3;
                    cp16(uA + aswz(row, c0), t9b + (size_t)row * K3 + kc + c0 * 8);
                }
            }
            asm volatile("cp.async.commit_group;");
            asm volatile("cp.async.wait_group 0;");
            __syncthreads();

            // fill B tile (t12 on the fly): row fr (cp = cp0+fr), 16 cols at fc8
            {
                size_t gb = (size_t)(cp0 + fr) * PP + nt0 + fc8;
                uint4 xa = *reinterpret_cast<const uint4*>(xb + gb);
                uint4 xc = *reinterpret_cast<const uint4*>(xb + gb + 8);
                uint4 sa = *reinterpret_cast<const uint4*>(t6b + gb);
                uint4 sc6 = *reinterpret_cast<const uint4*>(t6b + gb + 8);
                uint4 ta = *reinterpret_cast<const uint4*>(t3b + gb);
                uint4 tc = *reinterpret_cast<const uint4*>(t3b + gb + 8);
                unsigned xv[8] = {xa.x, xa.y, xa.z, xa.w, xc.x, xc.y, xc.z, xc.w};
                unsigned v6[8] = {sa.x, sa.y, sa.z, sa.w, sc6.x, sc6.y, sc6.z, sc6.w};
                unsigned v3[8] = {ta.x, ta.y, ta.z, ta.w, tc.x, tc.y, tc.z, tc.w};
                const int sh = 2 * j - 2;
                const int sbase = fr * 144 + 8 + fc8 + sh;
                const float sc0 = p12[j * 64 + h0 + (fc8 >> 6)];
                unsigned bout[8];
#pragma unroll
                for (int e = 0; e < 8; e++) {
                    int col = fc8 + 2 * e;
                    int w = (nt0 + col) & 63;
                    // pair validity for shift sh
                    bool valid = (sh == 0) || (sh < 0 ? (w >= 2) : (w <= 60));
                    __half2 xs = *reinterpret_cast<const __half2*>(&sX[sbase + 2 * e]);
                    float2 f1 = valid ? __half22float2(xs) : make_float2(0.f, 0.f);
                    float2 fx = __half22float2(*reinterpret_cast<__half2*>(&xv[e]));
                    float2 f6 = __half22float2(*reinterpret_cast<__half2*>(&v6[e]));
                    float2 f3 = __half22float2(*reinterpret_cast<__half2*>(&v3[e]));
                    float o0 = sc0 * fmaxf(f6.x, fmaxf(fx.x, f6.x) + fmaxf(f3.x, f1.x));
                    float o1 = sc0 * fmaxf(f6.y, fmaxf(fx.y, f6.y) + fmaxf(f3.y, f1.y));
                    bout[e] = pack2h(o0, o1);
                }
                char* sBp = reinterpret_cast<char*>(sB);
                *reinterpret_cast<uint4*>(sBp + bswz(fr, (tid & 7) * 2)) =
                    make_uint4(bout[0], bout[1], bout[2], bout[3]);
                *reinterpret_cast<uint4*>(sBp + bswz(fr, (tid & 7) * 2 + 1)) =
                    make_uint4(bout[4], bout[5], bout[6], bout[7]);
            }
            __syncthreads();

            // MMA over this 32-k slab
#pragma unroll
            for (int ks = 0; ks < 2; ks++) {
                unsigned bh[4][2];
                int row = ks * 16 + lr;
#pragma unroll
                for (int q = 0; q < 2; q++) {
                    int cb = (wn >> 3) + q * 2 + (lane >> 4);
                    ldsm4t(bh[2 * q][0], bh[2 * q][1], bh[2 * q + 1][0], bh[2 * q + 1][1],
                           uB + bswz(row, cb));
                }
                int ac0 = (lane >> 4) + ks * 2;
#pragma unroll
                for (int mt = 0; mt < 4; mt++) {
                    unsigned a0, a1, a2, a3;
                    ldsm4(a0, a1, a2, a3, uA + aswz(wm + mt * 16 + lr, ac0));
#pragma unroll
                    for (int nt = 0; nt < 4; nt++) {
                        float* a = acc[mt][nt];
                        mma_f16(a[0], a[1], a[2], a[3], a0, a1, a2, a3, bh[nt][0], bh[nt][1]);
                    }
                }
            }
            __syncthreads();
        }
    }

    const float scale = 0.051031036307982884f;   // 1/sqrt(384)
#pragma unroll
    for (int mt = 0; mt < 4; mt++) {
#pragma unroll
        for (int nt = 0; nt < 4; nt++) {
            int m0 = wm + mt * 16 + gq;
            int m1 = m0 + 8;
            int col = wn + nt * 8 + 2 * cq;
            float2 v0 = make_float2(acc[mt][nt][0] * scale, acc[mt][nt][1] * scale);
            float2 v1 = make_float2(acc[mt][nt][2] * scale, acc[mt][nt][3] * scale);
            float* cb = out + (size_t)nb * CH * PP + nt0;
            *reinterpret_cast<float2*>(&cb[(size_t)m0 * PP + col]) = v0;
            *reinterpret_cast<float2*>(&cb[(size_t)m1 * PP + col]) = v1;
        }
    }
}

// ---------------------------------------------------------------------------
extern "C" void kernel_launch(void* const* d_in, const int* in_sizes, int n_in,
                              void* d_out, int out_size)
{
    const float* x   = (const float*)d_in[0];
    const float* w3  = (const float*)d_in[1];
    const float* p5  = (const float*)d_in[2];
    const float* w6  = (const float*)d_in[3];
    const float* p8  = (const float*)d_in[4];
    const float* p12 = (const float*)d_in[5];
    float* out = (float*)d_out;

    const int SMB = NSTG * STG_BYTES;   // 65536 B
    cudaFuncSetAttribute(mma_gemm_kernel<0>, cudaFuncAttributeMaxDynamicSharedMemorySize, SMB);
    cudaFuncSetAttribute(mma_gemm_kernel<1>, cudaFuncAttributeMaxDynamicSharedMemorySize, SMB);
    cudaFuncSetAttribute(mma_gemm_kernel<2>, cudaFuncAttributeMaxDynamicSharedMemorySize, SMB);

    prep_w_kernel<<<(CH * K3) / 256, 256>>>(w3, w6);
    prep_xt5_kernel<<<(NB * CH * PP / 2) / 256, 256>>>(x, p5);      // xh + t5
    prep_t1m_kernel<<<(NB * 2 * CH * PP / 2) / 256, 256>>>();       // t1 m=0,2 planes
    mma_gemm_kernel<1><<<dim3(32, NB), 256, SMB>>>(p8);             // t6 + t7
    mma_gemm_kernel<0><<<dim3(32, NB), 256, SMB>>>(p8);             // t3
    mma_gemm_kernel<2><<<dim3(3, NB, SPLITS), 256, SMB>>>(p8);      // t9 partials
    reduce_t9s_kernel<<<(NB * CH * K3 / 2) / 256, 256>>>();
    mma_out_kernel<<<dim3(32, NB), 256>>>(p12, out);                // out (t12 fused)
}

// round 16
// speedup vs baseline: 1.2261x; 1.0930x over previous
#include <cuda_runtime.h>
#include <cuda_fp16.h>
#include <cstdint>

#define NB 32
#define CH 128
#define PP 4096        // H*W
#define K3 384         // 3*C  (k' = m*128 + cp m-major order everywhere)
#define SPLITS 4       // split-K for t9 (over p)
#define NSTG 4         // cp.async pipeline depth

// swizzled smem tile sizes (bytes)
#define A_BYTES 8192
#define B_BYTES 8192
#define STG_BYTES (A_BYTES + B_BYTES)   // 16384

// fp32 scratch (split-K partials only)
__device__ float g_t9p[SPLITS * NB * CH * K3];
// fp16 operands
__device__ __half g_xh  [NB * CH * PP];       // fp16 copy of x  (== t1 m=1 plane)
__device__ __half g_w3r [CH * K3];
__device__ __half g_w6r [CH * K3];
__device__ __half g_t1s2[NB * 2 * CH * PP];   // t1 planes m=0 (sh=-2), m=2 (sh=+2)
__device__ __half g_t5s [NB * CH * PP];
__device__ __half g_t3s [NB * CH * PP];
__device__ __half g_t6s [NB * CH * PP];
__device__ __half g_t7s [NB * CH * PP];
__device__ __half g_t9s [NB * CH * K3];

// ---------------------------------------------------------------------------
__device__ __forceinline__ unsigned pack2h(float v0, float v1)
{
    __half2 hh = __halves2half2(__float2half(v0), __float2half(v1));
    return *reinterpret_cast<unsigned*>(&hh);
}

__device__ __forceinline__ void mma_f16(float& d0, float& d1, float& d2, float& d3,
                                        unsigned a0, unsigned a1, unsigned a2, unsigned a3,
                                        unsigned b0, unsigned b1)
{
    asm volatile(
        "mma.sync.aligned.m16n8k16.row.col.f32.f16.f16.f32 "
        "{%0,%1,%2,%3},{%4,%5,%6,%7},{%8,%9},{%0,%1,%2,%3};\n"
        : "+f"(d0), "+f"(d1), "+f"(d2), "+f"(d3)
        : "r"(a0), "r"(a1), "r"(a2), "r"(a3), "r"(b0), "r"(b1));
}

__device__ __forceinline__ void ldsm4(unsigned& r0, unsigned& r1, unsigned& r2, unsigned& r3, unsigned a)
{
    asm volatile("ldmatrix.sync.aligned.m8n8.x4.shared.b16 {%0,%1,%2,%3},[%4];"
                 : "=r"(r0), "=r"(r1), "=r"(r2), "=r"(r3) : "r"(a));
}
__device__ __forceinline__ void ldsm4t(unsigned& r0, unsigned& r1, unsigned& r2, unsigned& r3, unsigned a)
{
    asm volatile("ldmatrix.sync.aligned.m8n8.x4.trans.shared.b16 {%0,%1,%2,%3},[%4];"
                 : "=r"(r0), "=r"(r1), "=r"(r2), "=r"(r3) : "r"(a));
}
__device__ __forceinline__ void cp16(unsigned d, const void* s)
{
    asm volatile("cp.async.ca.shared.global [%0], [%1], 16;" :: "r"(d), "l"(s));
}
__device__ __forceinline__ void cp16z(unsigned d, const void* s, int sz)
{
    asm volatile("cp.async.ca.shared.global [%0], [%1], 16, %2;" :: "r"(d), "l"(s), "r"(sz));
}

// A-style tile: 128 rows x 32 halfs (64B); 2 rows per 128B line.
__device__ __forceinline__ int aswz(int row, int c0)
{
    return (row >> 1) * 128 + (((((row & 1) << 2) | c0) ^ ((row >> 1) & 7)) << 4);
}
// B [k][n] tile: 32 rows x 128 halfs (256B rows, 16 chunks).
__device__ __forceinline__ int bswz(int row, int cb)
{
    return row * 256 + ((cb ^ (row & 7)) << 4);
}

// ---------------------------------------------------------------------------
// Prep kernels
// ---------------------------------------------------------------------------
__global__ void prep_w_kernel(const float* __restrict__ w3, const float* __restrict__ w6)
{
    int idx = blockIdx.x * 256 + threadIdx.x;
    int half_n = CH * K3 / 2;
    const float* src = (idx < half_n) ? w3 : w6;
    __half* dh = (idx < half_n) ? g_w3r : g_w6r;
    int i2 = (idx % half_n) * 2;
    int o = i2 / K3;
    int kp = i2 - o * K3;
    int m = kp >> 7;
    int cp = kp & 127;
    *reinterpret_cast<unsigned*>(&dh[i2]) =
        pack2h(src[o * K3 + 3 * cp + m], src[o * K3 + 3 * (cp + 1) + m]);
}

// ONE pass over fp32 x -> xh, t5, and both shifted t1 planes.
__global__ void prep_fused_kernel(const float* __restrict__ x, const float* __restrict__ p5)
{
    int i2 = (blockIdx.x * 256 + threadIdx.x) * 2;
    if (i2 >= NB * CH * PP) return;
    int p = i2 & (PP - 1);
    int w = p & 63;
    int rr = i2 >> 12;                 // nb*CH + c
    int nb = rr >> 7;
    const float* xr = x + (i2 - w);
    float x0 = xr[w], x1 = xr[w + 1];
    *reinterpret_cast<unsigned*>(&g_xh[i2]) = pack2h(x0, x1);
    // t5
    float v[2];
#pragma unroll
    for (int e = 0; e < 2; e++) {
        int we = w + e;
        float mx = (e == 0) ? x0 : x1;
        if (we >= 2) mx = fmaxf(mx, xr[we - 2]);
        if (we < 62) mx = fmaxf(mx, xr[we + 2]);
        v[e] = p5[p - w + we] * mx;
    }
    *reinterpret_cast<unsigned*>(&g_t5s[i2]) = pack2h(v[0], v[1]);
    // t1 planes: mi=0 -> shift -2, mi=1 -> shift +2
    size_t rowoff = (size_t)(i2 - ((size_t)nb << 19));     // offset within [2*CH*PP] batch? compute directly
    // plane indices
    size_t base0 = (((size_t)nb * 2 + 0) * CH) * PP + (i2 & ((CH * PP) - 1));
    size_t base2 = (((size_t)nb * 2 + 1) * CH) * PP + (i2 & ((CH * PP) - 1));
    float a0 = (w >= 2) ? xr[w - 2] : 0.f;
    float a1 = (w >= 1) ? xr[w - 1] : 0.f;
    float b0 = (w <= 61) ? xr[w + 2] : 0.f;
    float b1 = (w <= 60) ? xr[w + 3] : 0.f;
    *reinterpret_cast<unsigned*>(&g_t1s2[base0]) = pack2h(a0, a1);
    *reinterpret_cast<unsigned*>(&g_t1s2[base2]) = pack2h(b0, b1);
    (void)rowoff;
}

__global__ void reduce_t9s_kernel()
{
    int i2 = (blockIdx.x * 256 + threadIdx.x) * 2;
    float s0 = 0.f, s1 = 0.f;
#pragma unroll
    for (int u = 0; u < SPLITS; u++) {
        s0 += g_t9p[(size_t)u * NB * CH * K3 + i2];
        s1 += g_t9p[(size_t)u * NB * CH * K3 + i2 + 1];
    }
    *reinterpret_cast<unsigned*>(&g_t9s[i2]) =
        pack2h(s0 * (1.0f / 64.0f), s1 * (1.0f / 64.0f));
}

// selects the t1 plane for a given m (0/1/2)
__device__ __forceinline__ const __half* t1_base(int nb, int m)
{
    if (m == 1) return g_xh + (size_t)nb * CH * PP;
    return g_t1s2 + ((size_t)(nb * 2 + (m >> 1)) * CH) * PP;
}

// ---------------------------------------------------------------------------
// Merged t3+t6 GEMM (blockIdx.z: 0 -> t3 path, 1 -> t6 path). K=384.
// 256 threads, 8 warps 2m x 4n, warp tile 64x32, 4-stage pipeline, swizzled.
// ---------------------------------------------------------------------------
__global__ void __launch_bounds__(256, 2)
mma_gemm01_kernel(const float* __restrict__ p8)
{
    extern __shared__ __half smbuf[];
    const int md   = blockIdx.z;        // 0: t3 = w3r@t1 ; 1: t6 = w6r@t5(hsh)
    const int nb   = blockIdx.y;
    const int nt0  = blockIdx.x * 128;

    const int tid = threadIdx.x;
    const int wid = tid >> 5, lane = tid & 31;
    const int gq = lane >> 2, cq = lane & 3;
    const int lr = lane & 15;
    const int wm = (wid >> 2) * 64, wn = (wid & 3) * 32;
    const int h0 = nt0 >> 6;

    const unsigned sm0 = (unsigned)__cvta_generic_to_shared(smbuf);
    const __half* srcA = md ? g_w6r : g_w3r;

    float acc[4][4][4];
#pragma unroll
    for (int i = 0; i < 4; i++)
#pragma unroll
        for (int j = 0; j < 4; j++)
#pragma unroll
            for (int q = 0; q < 4; q++) acc[i][j][q] = 0.f;

    auto issue_stage = [&](int kt, int buf) {
        const unsigned sb = sm0 + buf * STG_BYTES;
#pragma unroll
        for (int q = 0; q < 2; q++) {
            int c = tid + q * 256;
            int row = c >> 2, c0 = c & 3;
            cp16(sb + aswz(row, c0), srcA + (size_t)row * K3 + kt + c0 * 8);
        }
        int m = kt >> 7, cp0 = kt & 127;
        if (md) {
#pragma unroll
            for (int u = 0; u < 2; u++) {
                int v = tid + u * 256;
                int r = v >> 4, ck = v & 15;
                int hc = ck >> 3, w8 = ck & 7;
                int cp = cp0 + r;
                int hp = h0 + 3 * m - 3 + hc;
                int valid = (hp >= 0 && hp < 64);
                int hpc = valid ? hp : 0;
                size_t s = (size_t)(nb * CH + cp) * PP + hpc * 64 + w8 * 8;
                cp16z(sb + A_BYTES + bswz(r, ck), g_t5s + s, valid ? 16 : 0);
            }
        } else {
            const __half* base = t1_base(nb, m);
#pragma unroll
            for (int q = 0; q < 2; q++) {
                int c = tid + q * 256;
                int row = c >> 4, cb = c & 15;
                size_t gidx = (size_t)(cp0 + row) * PP + nt0 + cb * 8;
                cp16(sb + A_BYTES + bswz(row, cb), base + gidx);
            }
        }
    };

    auto compute = [&](int buf) {
        const unsigned sb = sm0 + buf * STG_BYTES;
#pragma unroll
        for (int ks = 0; ks < 2; ks++) {
            unsigned bh[4][2];
            int row = ks * 16 + lr;
#pragma unroll
            for (int q = 0; q < 2; q++) {
                int cb = (wn >> 3) + q * 2 + (lane >> 4);
                ldsm4t(bh[2 * q][0], bh[2 * q][1], bh[2 * q + 1][0], bh[2 * q + 1][1],
                       sb + A_BYTES + bswz(row, cb));
            }
            int ac0 = (lane >> 4) + ks * 2;
#pragma unroll
            for (int mt = 0; mt < 4; mt++) {
                unsigned a0, a1, a2, a3;
                ldsm4(a0, a1, a2, a3, sb + aswz(wm + mt * 16 + lr, ac0));
#pragma unroll
                for (int nt = 0; nt < 4; nt++) {
                    float* a = acc[mt][nt];
                    mma_f16(a[0], a[1], a[2], a[3], a0, a1, a2, a3, bh[nt][0], bh[nt][1]);
                }
            }
        }
    };

    const int nstages = K3 / 32;
#pragma unroll
    for (int s = 0; s < NSTG; s++) {
        issue_stage(s * 32, s);
        asm volatile("cp.async.commit_group;");
    }
    int buf = 0;
    for (int it = 0; it < nstages; ++it) {
        int rem = nstages - 1 - it;
        if (rem >= 3)      asm volatile("cp.async.wait_group 3;");
        else if (rem == 2) asm volatile("cp.async.wait_group 2;");
        else if (rem == 1) asm volatile("cp.async.wait_group 1;");
        else               asm volatile("cp.async.wait_group 0;");
        __syncthreads();
        compute(buf);
        __syncthreads();
        if (it + NSTG < nstages) {
            issue_stage((it + NSTG) * 32, buf);
            asm volatile("cp.async.commit_group;");
        }
        buf = (buf + 1 == NSTG) ? 0 : buf + 1;
    }

#pragma unroll
    for (int mt = 0; mt < 4; mt++) {
#pragma unroll
        for (int nt = 0; nt < 4; nt++) {
            int m0 = wm + mt * 16 + gq;
            int m1 = m0 + 8;
            int col = wn + nt * 8 + 2 * cq;
            float2 v0 = make_float2(acc[mt][nt][0], acc[mt][nt][1]);
            float2 v1 = make_float2(acc[mt][nt][2], acc[mt][nt][3]);
            size_t i0 = ((size_t)nb * CH + m0) * PP + nt0 + col;
            size_t i1 = ((size_t)nb * CH + m1) * PP + nt0 + col;
            if (md == 0) {
                *reinterpret_cast<unsigned*>(&g_t3s[i0]) = pack2h(v0.x, v0.y);
                *reinterpret_cast<unsigned*>(&g_t3s[i1]) = pack2h(v1.x, v1.y);
            } else {
                *reinterpret_cast<unsigned*>(&g_t6s[i0]) = pack2h(v0.x, v0.y);
                *reinterpret_cast<unsigned*>(&g_t6s[i1]) = pack2h(v1.x, v1.y);
                float2 fx0 = __half22float2(*reinterpret_cast<const __half2*>(&g_xh[i0]));
                float2 fx1 = __half22float2(*reinterpret_cast<const __half2*>(&g_xh[i1]));
                float s0 = p8[m0], s1 = p8[m1];
                *reinterpret_cast<unsigned*>(&g_t7s[i0]) =
                    pack2h(s0 * fmaxf(fx0.x, v0.x), s0 * fmaxf(fx0.y, v0.y));
                *reinterpret_cast<unsigned*>(&g_t7s[i1]) =
                    pack2h(s1 * fmaxf(fx1.x, v1.x), s1 * fmaxf(fx1.y, v1.y));
            }
        }
    }
}

// ---------------------------------------------------------------------------
// t9 partials: t9p = t7 @ t1^T over p-slab (K = PP/SPLITS)
// ---------------------------------------------------------------------------
__global__ void __launch_bounds__(256, 2)
mma_gemm2_kernel()
{
    extern __shared__ __half smbuf[];
    const int KTOT  = PP / SPLITS;
    const int nb    = blockIdx.y;
    const int nt0   = blockIdx.x * 128;
    const int kbase = blockIdx.z * KTOT;

    const int tid = threadIdx.x;
    const int wid = tid >> 5, lane = tid & 31;
    const int gq = lane >> 2, cq = lane & 3;
    const int lr = lane & 15;
    const int wm = (wid >> 2) * 64, wn = (wid & 3) * 32;

    const unsigned sm0 = (unsigned)__cvta_generic_to_shared(smbuf);
    const __half* srcA  = g_t7s + (size_t)nb * CH * PP + kbase;
    const __half* srcB2 = t1_base(nb, nt0 >> 7) + kbase;

    float acc[4][4][4];
#pragma unroll
    for (int i = 0; i < 4; i++)
#pragma unroll
        for (int j = 0; j < 4; j++)
#pragma unroll
            for (int q = 0; q < 4; q++) acc[i][j][q] = 0.f;

    auto issue_stage = [&](int kt, int buf) {
        const unsigned sb = sm0 + buf * STG_BYTES;
#pragma unroll
        for (int q = 0; q < 2; q++) {
            int c = tid + q * 256;
            int row = c >> 2, c0 = c & 3;
            cp16(sb + aswz(row, c0), srcA + (size_t)row * PP + kt + c0 * 8);
            cp16(sb + A_BYTES + aswz(row, c0), srcB2 + (size_t)row * PP + kt + c0 * 8);
        }
    };

    auto compute = [&](int buf) {
        const unsigned sb = sm0 + buf * STG_BYTES;
#pragma unroll
        for (int ks = 0; ks < 2; ks++) {
            unsigned bh[4][2];
            int c0 = ((lane >> 3) & 1) + ks * 2;
#pragma unroll
            for (int q = 0; q < 2; q++) {
                int nrow = wn + q * 16 + (lane & 7) + ((lane >> 4) & 1) * 8;
                ldsm4(bh[2 * q][0], bh[2 * q][1], bh[2 * q + 1][0], bh[2 * q + 1][1],
                      sb + A_BYTES + aswz(nrow, c0));
            }
            int ac0 = (lane >> 4) + ks * 2;
#pragma unroll
            for (int mt = 0; mt < 4; mt++) {
                unsigned a0, a1, a2, a3;
                ldsm4(a0, a1, a2, a3, sb + aswz(wm + mt * 16 + lr, ac0));
#pragma unroll
                for (int nt = 0; nt < 4; nt++) {
                    float* a = acc[mt][nt];
                    mma_f16(a[0], a[1], a[2], a[3], a0, a1, a2, a3, bh[nt][0], bh[nt][1]);
                }
            }
        }
    };

    const int nstages = KTOT / 32;
#pragma unroll
    for (int s = 0; s < NSTG; s++) {
        issue_stage(s * 32, s);
        asm volatile("cp.async.commit_group;");
    }
    int buf = 0;
    for (int it = 0; it < nstages; ++it) {
        int rem = nstages - 1 - it;
        if (rem >= 3)      asm volatile("cp.async.wait_group 3;");
        else if (rem == 2) asm volatile("cp.async.wait_group 2;");
        else if (rem == 1) asm volatile("cp.async.wait_group 1;");
        else               asm volatile("cp.async.wait_group 0;");
        __syncthreads();
        compute(buf);
        __syncthreads();
        if (it + NSTG < nstages) {
            issue_stage((it + NSTG) * 32, buf);
            asm volatile("cp.async.commit_group;");
        }
        buf = (buf + 1 == NSTG) ? 0 : buf + 1;
    }

#pragma unroll
    for (int mt = 0; mt < 4; mt++) {
#pragma unroll
        for (int nt = 0; nt < 4; nt++) {
            int m0 = wm + mt * 16 + gq;
            int m1 = m0 + 8;
            int col = wn + nt * 8 + 2 * cq;
            float* cb = g_t9p + ((size_t)blockIdx.z * NB + nb) * CH * K3 + nt0;
            *reinterpret_cast<float2*>(&cb[(size_t)m0 * K3 + col]) =
                make_float2(acc[mt][nt][0], acc[mt][nt][1]);
            *reinterpret_cast<float2*>(&cb[(size_t)m1 * K3 + col]) =
                make_float2(acc[mt][nt][2], acc[mt][nt][3]);
        }
    }
}

// ---------------------------------------------------------------------------
// Fused output GEMM (t12 computed on the fly; see R15)
// ---------------------------------------------------------------------------
__global__ void __launch_bounds__(256, 2)
mma_out_kernel(const float* __restrict__ p12, float* __restrict__ out)
{
    __shared__ __align__(16) __half sA[4096];
    __shared__ __align__(16) __half sB[4096];
    __shared__ __align__(16) __half sX[32 * 144];

    const int nb  = blockIdx.y;
    const int nt0 = blockIdx.x * 128;
    const int h0  = nt0 >> 6;
    const int tid = threadIdx.x;
    const int wid = tid >> 5, lane = tid & 31;
    const int gq = lane >> 2, cq = lane & 3;
    const int lr = lane & 15;
    const int wm = (wid >> 2) * 64, wn = (wid & 3) * 32;

    const unsigned uA = (unsigned)__cvta_generic_to_shared(sA);
    const unsigned uB = (unsigned)__cvta_generic_to_shared(sB);
    const unsigned uX = (unsigned)__cvta_generic_to_shared(sX);

    const __half* xb  = g_xh  + (size_t)nb * CH * PP;
    const __half* t6b = g_t6s + (size_t)nb * CH * PP;
    const __half* t3b = g_t3s + (size_t)nb * CH * PP;
    const __half* t9b = g_t9s + (size_t)nb * CH * K3;

    float acc[4][4][4];
#pragma unroll
    for (int i = 0; i < 4; i++)
#pragma unroll
        for (int j = 0; j < 4; j++)
#pragma unroll
            for (int q = 0; q < 4; q++) acc[i][j][q] = 0.f;

    const int fr  = tid >> 3;
    const int fc8 = (tid & 7) * 16;

    for (int cpb = 0; cpb < 4; cpb++) {
        const int cp0 = cpb * 32;
#pragma unroll
        for (int q = 0; q < 3; q++) {
            int idx = tid + q * 256;
            if (idx < 576) {
                int row = idx / 18, ch = idx - row * 18;
                int p = nt0 - 8 + ch * 8;
                int valid = (p >= 0 && p + 8 <= PP);
                const __half* s = xb + (size_t)(cp0 + row) * PP + (valid ? p : 0);
                cp16z(uX + 2 * (row * 144 + ch * 8), s, valid ? 16 : 0);
            }
        }
        asm volatile("cp.async.commit_group;");

        for (int j = 0; j < 3; j++) {
            {
                int kc = j * 128 + cp0;
#pragma unroll
                for (int q = 0; q < 2; q++) {
                    int c = tid + q * 256;
                    int row = c >> 2, c0 = c & 3;
                    cp16(uA + aswz(row, c0), t9b + (size_t)row * K3 + kc + c0 * 8);
                }
            }
            asm volatile("cp.async.commit_group;");
            asm volatile("cp.async.wait_group 0;");
            __syncthreads();

            {
                size_t gb = (size_t)(cp0 + fr) * PP + nt0 + fc8;
                uint4 xa = *reinterpret_cast<const uint4*>(xb + gb);
                uint4 xc = *reinterpret_cast<const uint4*>(xb + gb + 8);
                uint4 sa = *reinterpret_cast<const uint4*>(t6b + gb);
                uint4 sc6 = *reinterpret_cast<const uint4*>(t6b + gb + 8);
                uint4 ta = *reinterpret_cast<const uint4*>(t3b + gb);
                uint4 tc = *reinterpret_cast<const uint4*>(t3b + gb + 8);
                unsigned xv[8] = {xa.x, xa.y, xa.z, xa.w, xc.x, xc.y, xc.z, xc.w};
                unsigned v6[8] = {sa.x, sa.y, sa.z, sa.w, sc6.x, sc6.y, sc6.z, sc6.w};
                unsigned v3[8] = {ta.x, ta.y, ta.z, ta.w, tc.x, tc.y, tc.z, tc.w};
                const int sh = 2 * j - 2;
                const int sbase = fr * 144 + 8 + fc8 + sh;
                const float sc0 = p12[j * 64 + h0 + (fc8 >> 6)];
                unsigned bout[8];
#pragma unroll
                for (int e = 0; e < 8; e++) {
                    int col = fc8 + 2 * e;
                    int w = (nt0 + col) & 63;
                    bool valid = (sh == 0) || (sh < 0 ? (w >= 2) : (w <= 60));
                    __half2 xs = *reinterpret_cast<const __half2*>(&sX[sbase + 2 * e]);
                    float2 f1 = valid ? __half22float2(xs) : make_float2(0.f, 0.f);
                    float2 fx = __half22float2(*reinterpret_cast<__half2*>(&xv[e]));
                    float2 f6 = __half22float2(*reinterpret_cast<__half2*>(&v6[e]));
                    float2 f3 = __half22float2(*reinterpret_cast<__half2*>(&v3[e]));
                    float o0 = sc0 * fmaxf(f6.x, fmaxf(fx.x, f6.x) + fmaxf(f3.x, f1.x));
                    float o1 = sc0 * fmaxf(f6.y, fmaxf(fx.y, f6.y) + fmaxf(f3.y, f1.y));
                    bout[e] = pack2h(o0, o1);
                }
                char* sBp = reinterpret_cast<char*>(sB);
                *reinterpret_cast<uint4*>(sBp + bswz(fr, (tid & 7) * 2)) =
                    make_uint4(bout[0], bout[1], bout[2], bout[3]);
                *reinterpret_cast<uint4*>(sBp + bswz(fr, (tid & 7) * 2 + 1)) =
                    make_uint4(bout[4], bout[5], bout[6], bout[7]);
            }
            __syncthreads();

#pragma unroll
            for (int ks = 0; ks < 2; ks++) {
                unsigned bh[4][2];
                int row = ks * 16 + lr;
#pragma unroll
                for (int q = 0; q < 2; q++) {
                    int cb = (wn >> 3) + q * 2 + (lane >> 4);
                    ldsm4t(bh[2 * q][0], bh[2 * q][1], bh[2 * q + 1][0], bh[2 * q + 1][1],
                           uB + bswz(row, cb));
                }
                int ac0 = (lane >> 4) + ks * 2;
#pragma unroll
                for (int mt = 0; mt < 4; mt++) {
                    unsigned a0, a1, a2, a3;
                    ldsm4(a0, a1, a2, a3, uA + aswz(wm + mt * 16 + lr, ac0));
#pragma unroll
                    for (int nt = 0; nt < 4; nt++) {
                        float* a = acc[mt][nt];
                        mma_f16(a[0], a[1], a[2], a[3], a0, a1, a2, a3, bh[nt][0], bh[nt][1]);
                    }
                }
            }
            __syncthreads();
        }
    }

    const float scale = 0.051031036307982884f;
#pragma unroll
    for (int mt = 0; mt < 4; mt++) {
#pragma unroll
        for (int nt = 0; nt < 4; nt++) {
            int m0 = wm + mt * 16 + gq;
            int m1 = m0 + 8;
            int col = wn + nt * 8 + 2 * cq;
            float* cb = out + (size_t)nb * CH * PP + nt0;
            *reinterpret_cast<float2*>(&cb[(size_t)m0 * PP + col]) =
                make_float2(acc[mt][nt][0] * scale, acc[mt][nt][1] * scale);
            *reinterpret_cast<float2*>(&cb[(size_t)m1 * PP + col]) =
                make_float2(acc[mt][nt][2] * scale, acc[mt][nt][3] * scale);
        }
    }
}

// ---------------------------------------------------------------------------
extern "C" void kernel_launch(void* const* d_in, const int* in_sizes, int n_in,
                              void* d_out, int out_size)
{
    const float* x   = (const float*)d_in[0];
    const float* w3  = (const float*)d_in[1];
    const float* p5  = (const float*)d_in[2];
    const float* w6  = (const float*)d_in[3];
    const float* p8  = (const float*)d_in[4];
    const float* p12 = (const float*)d_in[5];
    float* out = (float*)d_out;

    const int SMB = NSTG * STG_BYTES;   // 65536 B
    cudaFuncSetAttribute(mma_gemm01_kernel, cudaFuncAttributeMaxDynamicSharedMemorySize, SMB);
    cudaFuncSetAttribute(mma_gemm2_kernel,  cudaFuncAttributeMaxDynamicSharedMemorySize, SMB);

    prep_w_kernel<<<(CH * K3) / 256, 256>>>(w3, w6);
    prep_fused_kernel<<<(NB * CH * PP / 2) / 256, 256>>>(x, p5);      // xh,t5,t1 planes
    mma_gemm01_kernel<<<dim3(32, NB, 2), 256, SMB>>>(p8);             // t3 & t6+t7
    mma_gemm2_kernel<<<dim3(3, NB, SPLITS), 256, SMB>>>();            // t9 partials
    reduce_t9s_kernel<<<(NB * CH * K3 / 2) / 256, 256>>>();
    mma_out_kernel<<<dim3(32, NB), 256>>>(p12, out);                  // out (t12 fused)
}

// round 17
// speedup vs baseline: 1.2550x; 1.0236x over previous
#include <cuda_runtime.h>
#include <cuda_fp16.h>
#include <cstdint>

#define NB 32
#define CH 128
#define PP 4096        // H*W
#define K3 384         // 3*C  (k' = m*128 + cp m-major order everywhere)
#define SPLITS 2       // split-K for t9 (over p)
#define NSTG 4         // cp.async pipeline depth

// swizzled smem tile sizes (bytes)
#define A_BYTES 8192
#define B_BYTES 8192
#define STG_BYTES (A_BYTES + B_BYTES)   // 16384

// fp32 scratch (split-K partials only)
__device__ float g_t9p[SPLITS * NB * CH * K3];
// fp16 operands
__device__ __half g_xh  [NB * CH * PP];       // fp16 copy of x  (== t1 m=1 plane)
__device__ __half g_w3r [CH * K3];
__device__ __half g_w6r [CH * K3];
__device__ __half g_t1s2[NB * 2 * CH * PP];   // t1 planes m=0 (sh=-2), m=2 (sh=+2)
__device__ __half g_t5s [NB * CH * PP];
__device__ __half g_t3s [NB * CH * PP];
__device__ __half g_t6s [NB * CH * PP];
__device__ __half g_t7s [NB * CH * PP];
__device__ __half g_t9s [NB * CH * K3];

// ---------------------------------------------------------------------------
__device__ __forceinline__ unsigned pack2h(float v0, float v1)
{
    __half2 hh = __halves2half2(__float2half(v0), __float2half(v1));
    return *reinterpret_cast<unsigned*>(&hh);
}

__device__ __forceinline__ void mma_f16(float& d0, float& d1, float& d2, float& d3,
                                        unsigned a0, unsigned a1, unsigned a2, unsigned a3,
                                        unsigned b0, unsigned b1)
{
    asm volatile(
        "mma.sync.aligned.m16n8k16.row.col.f32.f16.f16.f32 "
        "{%0,%1,%2,%3},{%4,%5,%6,%7},{%8,%9},{%0,%1,%2,%3};\n"
        : "+f"(d0), "+f"(d1), "+f"(d2), "+f"(d3)
        : "r"(a0), "r"(a1), "r"(a2), "r"(a3), "r"(b0), "r"(b1));
}

__device__ __forceinline__ void ldsm4(unsigned& r0, unsigned& r1, unsigned& r2, unsigned& r3, unsigned a)
{
    asm volatile("ldmatrix.sync.aligned.m8n8.x4.shared.b16 {%0,%1,%2,%3},[%4];"
                 : "=r"(r0), "=r"(r1), "=r"(r2), "=r"(r3) : "r"(a));
}
__device__ __forceinline__ void ldsm4t(unsigned& r0, unsigned& r1, unsigned& r2, unsigned& r3, unsigned a)
{
    asm volatile("ldmatrix.sync.aligned.m8n8.x4.trans.shared.b16 {%0,%1,%2,%3},[%4];"
                 : "=r"(r0), "=r"(r1), "=r"(r2), "=r"(r3) : "r"(a));
}
__device__ __forceinline__ void cp16(unsigned d, const void* s)
{
    asm volatile("cp.async.ca.shared.global [%0], [%1], 16;" :: "r"(d), "l"(s));
}
__device__ __forceinline__ void cp16z(unsigned d, const void* s, int sz)
{
    asm volatile("cp.async.ca.shared.global [%0], [%1], 16, %2;" :: "r"(d), "l"(s), "r"(sz));
}

// A-style tile: 128 rows x 32 halfs (64B); 2 rows per 128B line.
__device__ __forceinline__ int aswz(int row, int c0)
{
    return (row >> 1) * 128 + (((((row & 1) << 2) | c0) ^ ((row >> 1) & 7)) << 4);
}
// B [k][n] tile: 32 rows x 128 halfs (256B rows, 16 chunks).
__device__ __forceinline__ int bswz(int row, int cb)
{
    return row * 256 + ((cb ^ (row & 7)) << 4);
}

// ---------------------------------------------------------------------------
// Prep kernels
// ---------------------------------------------------------------------------
__global__ void prep_w_kernel(const float* __restrict__ w3, const float* __restrict__ w6)
{
    int idx = blockIdx.x * 256 + threadIdx.x;
    int half_n = CH * K3 / 2;
    const float* src = (idx < half_n) ? w3 : w6;
    __half* dh = (idx < half_n) ? g_w3r : g_w6r;
    int i2 = (idx % half_n) * 2;
    int o = i2 / K3;
    int kp = i2 - o * K3;
    int m = kp >> 7;
    int cp = kp & 127;
    *reinterpret_cast<unsigned*>(&dh[i2]) =
        pack2h(src[o * K3 + 3 * cp + m], src[o * K3 + 3 * (cp + 1) + m]);
}

// ONE pass over fp32 x -> xh, t5, and both shifted t1 planes.
__global__ void prep_fused_kernel(const float* __restrict__ x, const float* __restrict__ p5)
{
    int i2 = (blockIdx.x * 256 + threadIdx.x) * 2;
    if (i2 >= NB * CH * PP) return;
    int p = i2 & (PP - 1);
    int w = p & 63;
    int rr = i2 >> 12;                 // nb*CH + c
    int nb = rr >> 7;
    const float* xr = x + (i2 - w);
    float x0 = xr[w], x1 = xr[w + 1];
    *reinterpret_cast<unsigned*>(&g_xh[i2]) = pack2h(x0, x1);
    float v[2];
#pragma unroll
    for (int e = 0; e < 2; e++) {
        int we = w + e;
        float mx = (e == 0) ? x0 : x1;
        if (we >= 2) mx = fmaxf(mx, xr[we - 2]);
        if (we < 62) mx = fmaxf(mx, xr[we + 2]);
        v[e] = p5[p - w + we] * mx;
    }
    *reinterpret_cast<unsigned*>(&g_t5s[i2]) = pack2h(v[0], v[1]);
    size_t base0 = (((size_t)nb * 2 + 0) * CH) * PP + (i2 & ((CH * PP) - 1));
    size_t base2 = (((size_t)nb * 2 + 1) * CH) * PP + (i2 & ((CH * PP) - 1));
    float a0 = (w >= 2) ? xr[w - 2] : 0.f;
    float a1 = (w >= 1) ? xr[w - 1] : 0.f;
    float b0 = (w <= 61) ? xr[w + 2] : 0.f;
    float b1 = (w <= 60) ? xr[w + 3] : 0.f;
    *reinterpret_cast<unsigned*>(&g_t1s2[base0]) = pack2h(a0, a1);
    *reinterpret_cast<unsigned*>(&g_t1s2[base2]) = pack2h(b0, b1);
}

__global__ void reduce_t9s_kernel()
{
    int i2 = (blockIdx.x * 256 + threadIdx.x) * 2;
    float s0 = 0.f, s1 = 0.f;
#pragma unroll
    for (int u = 0; u < SPLITS; u++) {
        s0 += g_t9p[(size_t)u * NB * CH * K3 + i2];
        s1 += g_t9p[(size_t)u * NB * CH * K3 + i2 + 1];
    }
    *reinterpret_cast<unsigned*>(&g_t9s[i2]) =
        pack2h(s0 * (1.0f / 64.0f), s1 * (1.0f / 64.0f));
}

// selects the t1 plane for a given m (0/1/2)
__device__ __forceinline__ const __half* t1_base(int nb, int m)
{
    if (m == 1) return g_xh + (size_t)nb * CH * PP;
    return g_t1s2 + ((size_t)(nb * 2 + (m >> 1)) * CH) * PP;
}

// ---------------------------------------------------------------------------
// Merged t3+t6 GEMM (blockIdx.z: 0 -> t3 path, 1 -> t6 path). K=384.
// ---------------------------------------------------------------------------
__global__ void __launch_bounds__(256, 2)
mma_gemm01_kernel(const float* __restrict__ p8)
{
    extern __shared__ __half smbuf[];
    const int md   = blockIdx.z;
    const int nb   = blockIdx.y;
    const int nt0  = blockIdx.x * 128;

    const int tid = threadIdx.x;
    const int wid = tid >> 5, lane = tid & 31;
    const int gq = lane >> 2, cq = lane & 3;
    const int lr = lane & 15;
    const int wm = (wid >> 2) * 64, wn = (wid & 3) * 32;
    const int h0 = nt0 >> 6;

    const unsigned sm0 = (unsigned)__cvta_generic_to_shared(smbuf);
    const __half* srcA = md ? g_w6r : g_w3r;

    float acc[4][4][4];
#pragma unroll
    for (int i = 0; i < 4; i++)
#pragma unroll
        for (int j = 0; j < 4; j++)
#pragma unroll
            for (int q = 0; q < 4; q++) acc[i][j][q] = 0.f;

    auto issue_stage = [&](int kt, int buf) {
        const unsigned sb = sm0 + buf * STG_BYTES;
#pragma unroll
        for (int q = 0; q < 2; q++) {
            int c = tid + q * 256;
            int row = c >> 2, c0 = c & 3;
            cp16(sb + aswz(row, c0), srcA + (size_t)row * K3 + kt + c0 * 8);
        }
        int m = kt >> 7, cp0 = kt & 127;
        if (md) {
#pragma unroll
            for (int u = 0; u < 2; u++) {
                int v = tid + u * 256;
                int r = v >> 4, ck = v & 15;
                int hc = ck >> 3, w8 = ck & 7;
                int cp = cp0 + r;
                int hp = h0 + 3 * m - 3 + hc;
                int valid = (hp >= 0 && hp < 64);
                int hpc = valid ? hp : 0;
                size_t s = (size_t)(nb * CH + cp) * PP + hpc * 64 + w8 * 8;
                cp16z(sb + A_BYTES + bswz(r, ck), g_t5s + s, valid ? 16 : 0);
            }
        } else {
            const __half* base = t1_base(nb, m);
#pragma unroll
            for (int q = 0; q < 2; q++) {
                int c = tid + q * 256;
                int row = c >> 4, cb = c & 15;
                size_t gidx = (size_t)(cp0 + row) * PP + nt0 + cb * 8;
                cp16(sb + A_BYTES + bswz(row, cb), base + gidx);
            }
        }
    };

    auto compute = [&](int buf) {
        const unsigned sb = sm0 + buf * STG_BYTES;
#pragma unroll
        for (int ks = 0; ks < 2; ks++) {
            unsigned bh[4][2];
            int row = ks * 16 + lr;
#pragma unroll
            for (int q = 0; q < 2; q++) {
                int cb = (wn >> 3) + q * 2 + (lane >> 4);
                ldsm4t(bh[2 * q][0], bh[2 * q][1], bh[2 * q + 1][0], bh[2 * q + 1][1],
                       sb + A_BYTES + bswz(row, cb));
            }
            int ac0 = (lane >> 4) + ks * 2;
#pragma unroll
            for (int mt = 0; mt < 4; mt++) {
                unsigned a0, a1, a2, a3;
                ldsm4(a0, a1, a2, a3, sb + aswz(wm + mt * 16 + lr, ac0));
#pragma unroll
                for (int nt = 0; nt < 4; nt++) {
                    float* a = acc[mt][nt];
                    mma_f16(a[0], a[1], a[2], a[3], a0, a1, a2, a3, bh[nt][0], bh[nt][1]);
                }
            }
        }
    };

    const int nstages = K3 / 32;
#pragma unroll
    for (int s = 0; s < NSTG; s++) {
        issue_stage(s * 32, s);
        asm volatile("cp.async.commit_group;");
    }
    int buf = 0;
    for (int it = 0; it < nstages; ++it) {
        int rem = nstages - 1 - it;
        if (rem >= 3)      asm volatile("cp.async.wait_group 3;");
        else if (rem == 2) asm volatile("cp.async.wait_group 2;");
        else if (rem == 1) asm volatile("cp.async.wait_group 1;");
        else               asm volatile("cp.async.wait_group 0;");
        __syncthreads();
        compute(buf);
        __syncthreads();
        if (it + NSTG < nstages) {
            issue_stage((it + NSTG) * 32, buf);
            asm volatile("cp.async.commit_group;");
        }
        buf = (buf + 1 == NSTG) ? 0 : buf + 1;
    }

#pragma unroll
    for (int mt = 0; mt < 4; mt++) {
#pragma unroll
        for (int nt = 0; nt < 4; nt++) {
            int m0 = wm + mt * 16 + gq;
            int m1 = m0 + 8;
            int col = wn + nt * 8 + 2 * cq;
            float2 v0 = make_float2(acc[mt][nt][0], acc[mt][nt][1]);
            float2 v1 = make_float2(acc[mt][nt][2], acc[mt][nt][3]);
            size_t i0 = ((size_t)nb * CH + m0) * PP + nt0 + col;
            size_t i1 = ((size_t)nb * CH + m1) * PP + nt0 + col;
            if (md == 0) {
                *reinterpret_cast<unsigned*>(&g_t3s[i0]) = pack2h(v0.x, v0.y);
                *reinterpret_cast<unsigned*>(&g_t3s[i1]) = pack2h(v1.x, v1.y);
            } else {
                *reinterpret_cast<unsigned*>(&g_t6s[i0]) = pack2h(v0.x, v0.y);
                *reinterpret_cast<unsigned*>(&g_t6s[i1]) = pack2h(v1.x, v1.y);
                float2 fx0 = __half22float2(*reinterpret_cast<const __half2*>(&g_xh[i0]));
                float2 fx1 = __half22float2(*reinterpret_cast<const __half2*>(&g_xh[i1]));
                float s0 = p8[m0], s1 = p8[m1];
                *reinterpret_cast<unsigned*>(&g_t7s[i0]) =
                    pack2h(s0 * fmaxf(fx0.x, v0.x), s0 * fmaxf(fx0.y, v0.y));
                *reinterpret_cast<unsigned*>(&g_t7s[i1]) =
                    pack2h(s1 * fmaxf(fx1.x, v1.x), s1 * fmaxf(fx1.y, v1.y));
            }
        }
    }
}

// ---------------------------------------------------------------------------
// t9 partials: t9p = t7 @ t1^T over p-slab (K = PP/SPLITS)
// ---------------------------------------------------------------------------
__global__ void __launch_bounds__(256, 2)
mma_gemm2_kernel()
{
    extern __shared__ __half smbuf[];
    const int KTOT  = PP / SPLITS;
    const int nb    = blockIdx.y;
    const int nt0   = blockIdx.x * 128;
    const int kbase = blockIdx.z * KTOT;

    const int tid = threadIdx.x;
    const int wid = tid >> 5, lane = tid & 31;
    const int gq = lane >> 2, cq = lane & 3;
    const int lr = lane & 15;
    const int wm = (wid >> 2) * 64, wn = (wid & 3) * 32;

    const unsigned sm0 = (unsigned)__cvta_generic_to_shared(smbuf);
    const __half* srcA  = g_t7s + (size_t)nb * CH * PP + kbase;
    const __half* srcB2 = t1_base(nb, nt0 >> 7) + kbase;

    float acc[4][4][4];
#pragma unroll
    for (int i = 0; i < 4; i++)
#pragma unroll
        for (int j = 0; j < 4; j++)
#pragma unroll
            for (int q = 0; q < 4; q++) acc[i][j][q] = 0.f;

    auto issue_stage = [&](int kt, int buf) {
        const unsigned sb = sm0 + buf * STG_BYTES;
#pragma unroll
        for (int q = 0; q < 2; q++) {
            int c = tid + q * 256;
            int row = c >> 2, c0 = c & 3;
            cp16(sb + aswz(row, c0), srcA + (size_t)row * PP + kt + c0 * 8);
            cp16(sb + A_BYTES + aswz(row, c0), srcB2 + (size_t)row * PP + kt + c0 * 8);
        }
    };

    auto compute = [&](int buf) {
        const unsigned sb = sm0 + buf * STG_BYTES;
#pragma unroll
        for (int ks = 0; ks < 2; ks++) {
            unsigned bh[4][2];
            int c0 = ((lane >> 3) & 1) + ks * 2;
#pragma unroll
            for (int q = 0; q < 2; q++) {
                int nrow = wn + q * 16 + (lane & 7) + ((lane >> 4) & 1) * 8;
                ldsm4(bh[2 * q][0], bh[2 * q][1], bh[2 * q + 1][0], bh[2 * q + 1][1],
                      sb + A_BYTES + aswz(nrow, c0));
            }
            int ac0 = (lane >> 4) + ks * 2;
#pragma unroll
            for (int mt = 0; mt < 4; mt++) {
                unsigned a0, a1, a2, a3;
                ldsm4(a0, a1, a2, a3, sb + aswz(wm + mt * 16 + lr, ac0));
#pragma unroll
                for (int nt = 0; nt < 4; nt++) {
                    float* a = acc[mt][nt];
                    mma_f16(a[0], a[1], a[2], a[3], a0, a1, a2, a3, bh[nt][0], bh[nt][1]);
                }
            }
        }
    };

    const int nstages = KTOT / 32;
#pragma unroll
    for (int s = 0; s < NSTG; s++) {
        issue_stage(s * 32, s);
        asm volatile("cp.async.commit_group;");
    }
    int buf = 0;
    for (int it = 0; it < nstages; ++it) {
        int rem = nstages - 1 - it;
        if (rem >= 3)      asm volatile("cp.async.wait_group 3;");
        else if (rem == 2) asm volatile("cp.async.wait_group 2;");
        else if (rem == 1) asm volatile("cp.async.wait_group 1;");
        else               asm volatile("cp.async.wait_group 0;");
        __syncthreads();
        compute(buf);
        __syncthreads();
        if (it + NSTG < nstages) {
            issue_stage((it + NSTG) * 32, buf);
            asm volatile("cp.async.commit_group;");
        }
        buf = (buf + 1 == NSTG) ? 0 : buf + 1;
    }

#pragma unroll
    for (int mt = 0; mt < 4; mt++) {
#pragma unroll
        for (int nt = 0; nt < 4; nt++) {
            int m0 = wm + mt * 16 + gq;
            int m1 = m0 + 8;
            int col = wn + nt * 8 + 2 * cq;
            float* cb = g_t9p + ((size_t)blockIdx.z * NB + nb) * CH * K3 + nt0;
            *reinterpret_cast<float2*>(&cb[(size_t)m0 * K3 + col]) =
                make_float2(acc[mt][nt][0], acc[mt][nt][1]);
            *reinterpret_cast<float2*>(&cb[(size_t)m1 * K3 + col]) =
                make_float2(acc[mt][nt][2], acc[mt][nt][3]);
        }
    }
}

// ---------------------------------------------------------------------------
// Fused output GEMM (t12 computed on the fly), double-buffered A + early LDGs.
// ---------------------------------------------------------------------------
__global__ void __launch_bounds__(256, 2)
mma_out_kernel(const float* __restrict__ p12, float* __restrict__ out)
{
    __shared__ __align__(16) __half sA[2][4096];
    __shared__ __align__(16) __half sB[4096];
    __shared__ __align__(16) __half sX[32 * 144];

    const int nb  = blockIdx.y;
    const int nt0 = blockIdx.x * 128;
    const int h0  = nt0 >> 6;
    const int tid = threadIdx.x;
    const int wid = tid >> 5, lane = tid & 31;
    const int gq = lane >> 2, cq = lane & 3;
    const int lr = lane & 15;
    const int wm = (wid >> 2) * 64, wn = (wid & 3) * 32;

    const unsigned uA0 = (unsigned)__cvta_generic_to_shared(&sA[0][0]);
    const unsigned uB  = (unsigned)__cvta_generic_to_shared(sB);
    const unsigned uX  = (unsigned)__cvta_generic_to_shared(sX);

    const __half* xb  = g_xh  + (size_t)nb * CH * PP;
    const __half* t6b = g_t6s + (size_t)nb * CH * PP;
    const __half* t3b = g_t3s + (size_t)nb * CH * PP;
    const __half* t9b = g_t9s + (size_t)nb * CH * K3;

    float acc[4][4][4];
#pragma unroll
    for (int i = 0; i < 4; i++)
#pragma unroll
        for (int j = 0; j < 4; j++)
#pragma unroll
            for (int q = 0; q < 4; q++) acc[i][j][q] = 0.f;

    const int fr  = tid >> 3;
    const int fc8 = (tid & 7) * 16;

    auto issueA = [&](int j, int cp0) {
        int kc = j * 128 + cp0;
        unsigned dst = uA0 + (j & 1) * 8192;
#pragma unroll
        for (int q = 0; q < 2; q++) {
            int c = tid + q * 256;
            int row = c >> 2, c0 = c & 3;
            cp16(dst + aswz(row, c0), t9b + (size_t)row * K3 + kc + c0 * 8);
        }
    };

    for (int cpb = 0; cpb < 4; cpb++) {
        const int cp0 = cpb * 32;
        // group G0: sX window + A(j=0)
#pragma unroll
        for (int q = 0; q < 3; q++) {
            int idx = tid + q * 256;
            if (idx < 576) {
                int row = idx / 18, ch = idx - row * 18;
                int p = nt0 - 8 + ch * 8;
                int valid = (p >= 0 && p + 8 <= PP);
                const __half* s = xb + (size_t)(cp0 + row) * PP + (valid ? p : 0);
                cp16z(uX + 2 * (row * 144 + ch * 8), s, valid ? 16 : 0);
            }
        }
        issueA(0, cp0);
        asm volatile("cp.async.commit_group;");

        // hoisted invariant LDGs (same addresses for all j in this cpb)
        size_t gb = (size_t)(cp0 + fr) * PP + nt0 + fc8;
        uint4 xa = *reinterpret_cast<const uint4*>(xb + gb);
        uint4 xc = *reinterpret_cast<const uint4*>(xb + gb + 8);
        uint4 sa = *reinterpret_cast<const uint4*>(t6b + gb);
        uint4 sc6 = *reinterpret_cast<const uint4*>(t6b + gb + 8);
        uint4 ta = *reinterpret_cast<const uint4*>(t3b + gb);
        uint4 tc = *reinterpret_cast<const uint4*>(t3b + gb + 8);

        for (int j = 0; j < 3; j++) {
            if (j < 2) {
                issueA(j + 1, cp0);
                asm volatile("cp.async.commit_group;");
                asm volatile("cp.async.wait_group 1;");
            } else {
                asm volatile("cp.async.wait_group 0;");
            }
            __syncthreads();

            // fill B tile (t12 on the fly) from registers + sX
            {
                unsigned xv[8] = {xa.x, xa.y, xa.z, xa.w, xc.x, xc.y, xc.z, xc.w};
                unsigned v6[8] = {sa.x, sa.y, sa.z, sa.w, sc6.x, sc6.y, sc6.z, sc6.w};
                unsigned v3[8] = {ta.x, ta.y, ta.z, ta.w, tc.x, tc.y, tc.z, tc.w};
                const int sh = 2 * j - 2;
                const int sbase = fr * 144 + 8 + fc8 + sh;
                const float sc0 = p12[j * 64 + h0 + (fc8 >> 6)];
                unsigned bout[8];
#pragma unroll
                for (int e = 0; e < 8; e++) {
                    int col = fc8 + 2 * e;
                    int w = (nt0 + col) & 63;
                    bool valid = (sh == 0) || (sh < 0 ? (w >= 2) : (w <= 60));
                    __half2 xs = *reinterpret_cast<const __half2*>(&sX[sbase + 2 * e]);
                    float2 f1 = valid ? __half22float2(xs) : make_float2(0.f, 0.f);
                    float2 fx = __half22float2(*reinterpret_cast<__half2*>(&xv[e]));
                    float2 f6 = __half22float2(*reinterpret_cast<__half2*>(&v6[e]));
                    float2 f3 = __half22float2(*reinterpret_cast<__half2*>(&v3[e]));
                    float o0 = sc0 * fmaxf(f6.x, fmaxf(fx.x, f6.x) + fmaxf(f3.x, f1.x));
                    float o1 = sc0 * fmaxf(f6.y, fmaxf(fx.y, f6.y) + fmaxf(f3.y, f1.y));
                    bout[e] = pack2h(o0, o1);
                }
                char* sBp = reinterpret_cast<char*>(sB);
                *reinterpret_cast<uint4*>(sBp + bswz(fr, (tid & 7) * 2)) =
                    make_uint4(bout[0], bout[1], bout[2], bout[3]);
                *reinterpret_cast<uint4*>(sBp + bswz(fr, (tid & 7) * 2 + 1)) =
                    make_uint4(bout[4], bout[5], bout[6], bout[7]);
            }
            __syncthreads();

            const unsigned uA = uA0 + (j & 1) * 8192;
#pragma unroll
            for (int ks = 0; ks < 2; ks++) {
                unsigned bh[4][2];
                int row = ks * 16 + lr;
#pragma unroll
                for (int q = 0; q < 2; q++) {
                    int cb = (wn >> 3) + q * 2 + (lane >> 4);
                    ldsm4t(bh[2 * q][0], bh[2 * q][1], bh[2 * q + 1][0], bh[2 * q + 1][1],
                           uB + bswz(row, cb));
                }
                int ac0 = (lane >> 4) + ks * 2;
#pragma unroll
                for (int mt = 0; mt < 4; mt++) {
                    unsigned a0, a1, a2, a3;
                    ldsm4(a0, a1, a2, a3, uA + aswz(wm + mt * 16 + lr, ac0));
#pragma unroll
                    for (int nt = 0; nt < 4; nt++) {
                        float* a = acc[mt][nt];
                        mma_f16(a[0], a[1], a[2], a[3], a0, a1, a2, a3, bh[nt][0], bh[nt][1]);
                    }
                }
            }
            __syncthreads();
        }
    }

    const float scale = 0.051031036307982884f;
#pragma unroll
    for (int mt = 0; mt < 4; mt++) {
#pragma unroll
        for (int nt = 0; nt < 4; nt++) {
            int m0 = wm + mt * 16 + gq;
            int m1 = m0 + 8;
            int col = wn + nt * 8 + 2 * cq;
            float* cb = out + (size_t)nb * CH * PP + nt0;
            *reinterpret_cast<float2*>(&cb[(size_t)m0 * PP + col]) =
                make_float2(acc[mt][nt][0] * scale, acc[mt][nt][1] * scale);
            *reinterpret_cast<float2*>(&cb[(size_t)m1 * PP + col]) =
                make_float2(acc[mt][nt][2] * scale, acc[mt][nt][3] * scale);
        }
    }
}

// ---------------------------------------------------------------------------
extern "C" void kernel_launch(void* const* d_in, const int* in_sizes, int n_in,
                              void* d_out, int out_size)
{
    const float* x   = (const float*)d_in[0];
    const float* w3  = (const float*)d_in[1];
    const float* p5  = (const float*)d_in[2];
    const float* w6  = (const float*)d_in[3];
    const float* p8  = (const float*)d_in[4];
    const float* p12 = (const float*)d_in[5];
    float* out = (float*)d_out;

    const int SMB = NSTG * STG_BYTES;   // 65536 B
    cudaFuncSetAttribute(mma_gemm01_kernel, cudaFuncAttributeMaxDynamicSharedMemorySize, SMB);
    cudaFuncSetAttribute(mma_gemm2_kernel,  cudaFuncAttributeMaxDynamicSharedMemorySize, SMB);

    prep_w_kernel<<<(CH * K3) / 256, 256>>>(w3, w6);
    prep_fused_kernel<<<(NB * CH * PP / 2) / 256, 256>>>(x, p5);      // xh,t5,t1 planes
    mma_gemm01_kernel<<<dim3(32, NB, 2), 256, SMB>>>(p8);             // t3 & t6+t7
    mma_gemm2_kernel<<<dim3(3, NB, SPLITS), 256, SMB>>>();            // t9 partials
    reduce_t9s_kernel<<<(NB * CH * K3 / 2) / 256, 256>>>();
    mma_out_kernel<<<dim3(32, NB), 256>>>(p12, out);                  // out (t12 fused)
}